// round 13
// baseline (speedup 1.0000x reference)
#include <cuda_runtime.h>
#include <cuda_fp16.h>
#include <math.h>
#include <stdint.h>

#define N 4096
#define NHEADS 8
#define NHID 64
#define NFEAT 512
#define NOUT 56

// ---------------- device scratch ----------------
__device__ __half g_xh[(size_t)N * NFEAT];
__device__ __half g_Wh[(size_t)NHEADS * NFEAT * NHID];
__device__ __half g_Hf16[(size_t)NHEADS * N * NHID];
__device__ uint32_t g_adjbits[(size_t)N * 128];
__device__ __half g_E1h[NHEADS * N], g_E1bh[NHEADS * N];
__device__ __half g_E2h[NHEADS * N], g_E2bh[NHEADS * N];
__device__ float g_num1[(size_t)NHEADS * N * 64];   // per-head attention numerators
__device__ float g_den1[NHEADS * N];
__device__ __half g_H2f16[(size_t)N * 64];   // col 56 = 1.0 (den trick), 57-63 = 0
__device__ __half g_E1oh[N], g_E1boh[N], g_E2oh[N], g_E2boh[N];
__device__ float g_num2[N * NOUT];
__device__ float g_den2[N];

// ---------------- helpers ----------------
__device__ __forceinline__ uint32_t s2u(const void* p) {
    uint32_t a;
    asm("{ .reg .u64 t; cvta.to.shared.u64 t, %1; cvt.u32.u64 %0, t; }" : "=r"(a) : "l"(p));
    return a;
}
#define LDSM_X4(r0, r1, r2, r3, a) \
    asm volatile("ldmatrix.sync.aligned.m8n8.x4.shared.b16 {%0,%1,%2,%3}, [%4];" \
                 : "=r"(r0), "=r"(r1), "=r"(r2), "=r"(r3) : "r"(a))
#define LDSM_X4T(r0, r1, r2, r3, a) \
    asm volatile("ldmatrix.sync.aligned.m8n8.x4.trans.shared.b16 {%0,%1,%2,%3}, [%4];" \
                 : "=r"(r0), "=r"(r1), "=r"(r2), "=r"(r3) : "r"(a))

__device__ __forceinline__ void mma16816(float* c, uint32_t a0, uint32_t a1, uint32_t a2,
                                         uint32_t a3, uint32_t b0, uint32_t b1) {
    asm volatile(
        "mma.sync.aligned.m16n8k16.row.col.f32.f16.f16.f32 "
        "{%0,%1,%2,%3}, {%4,%5,%6,%7}, {%8,%9}, {%0,%1,%2,%3};"
        : "+f"(c[0]), "+f"(c[1]), "+f"(c[2]), "+f"(c[3])
        : "r"(a0), "r"(a1), "r"(a2), "r"(a3), "r"(b0), "r"(b1));
}
__device__ __forceinline__ uint32_t packh2(float lo, float hi) {
    __half2 h = __floats2half2_rn(lo, hi);
    return *(uint32_t*)&h;
}
__device__ __forceinline__ uint32_t h2u(__half2 h) { return *(uint32_t*)&h; }
__device__ __forceinline__ uint32_t bits2mask(uint32_t b) {
    return ((b & 1u) ? 0x0000FFFFu : 0u) | ((b & 2u) ? 0xFFFF0000u : 0u);
}
__device__ __forceinline__ void cpa16(uint32_t dst, const void* src) {
    asm volatile("cp.async.cg.shared.global [%0], [%1], 16;" :: "r"(dst), "l"(src));
}
#define CP_COMMIT() asm volatile("cp.async.commit_group;")
#define CP_WAIT1()  asm volatile("cp.async.wait_group 1;")
#define CP_WAIT0()  asm volatile("cp.async.wait_group 0;")

// ---------------- KA: merged init (zero + fp16 convert + adj bitmask) ----------------
__global__ __launch_bounds__(256) void kA_init(const float* __restrict__ x,
                                               const float* __restrict__ Ws,
                                               const int* __restrict__ adj) {
    int t = threadIdx.x;
    int gid = blockIdx.x * 256 + t;
    int stride = gridDim.x * 256;
    int w = gid >> 5, lane = t & 31;
    int row = w >> 2, quarter = w & 3;
    const int4* src = (const int4*)(adj + (size_t)row * N + quarter * 1024);
    uint32_t* dstw = g_adjbits + (size_t)row * 128 + quarter * 32;
#pragma unroll
    for (int it = 0; it < 8; it++) {
        int4 v = src[it * 32 + lane];
        uint32_t nib = (uint32_t)(v.x > 0) | ((uint32_t)(v.y > 0) << 1)
                     | ((uint32_t)(v.z > 0) << 2) | ((uint32_t)(v.w > 0) << 3);
        uint32_t word = nib << (4 * (lane & 7));
        word |= __shfl_xor_sync(0xffffffffu, word, 1);
        word |= __shfl_xor_sync(0xffffffffu, word, 2);
        word |= __shfl_xor_sync(0xffffffffu, word, 4);
        if ((lane & 7) == 0) dstw[it * 4 + (lane >> 3)] = word;
    }
    for (int i = gid; i < N * NFEAT / 2; i += stride) {
        float2 v = ((const float2*)x)[i];
        ((__half2*)g_xh)[i] = __floats2half2_rn(v.x, v.y);
    }
    for (int i = gid; i < NHEADS * NFEAT * NHID / 2; i += stride) {
        float2 v = ((const float2*)Ws)[i];
        ((__half2*)g_Wh)[i] = __floats2half2_rn(v.x, v.y);
    }
    for (int i = gid; i < NHEADS * N * 64; i += stride) g_num1[i] = 0.f;
    for (int i = gid; i < NHEADS * N; i += stride) g_den1[i] = 0.f;
    for (int i = gid; i < N * NOUT; i += stride) g_num2[i] = 0.f;
    for (int i = gid; i < N; i += stride) g_den2[i] = 0.f;
}

// ---------------- dummy: keeps k3 in the profiler's capture slot ----------------
__global__ void k_nop() {}

// ---------------- K1: H = x @ Ws, 64x64 tile, 128 threads, fused exp epilogue ----------------
#define K1_AS 80
#define K1_BS 144
__global__ __launch_bounds__(128) void k1_mma(const float* __restrict__ As_) {
    __shared__ __align__(16) char Asm[2][64 * K1_AS];
    __shared__ __align__(16) char Bsm[2][32 * K1_BS];
    __shared__ __align__(16) __half Hsm[64 * 64];
    uint32_t Abase = s2u(Asm), Bbase = s2u(Bsm);
    int t = threadIdx.x, w = t >> 5, l = t & 31;
    int i0 = blockIdx.x * 64;
    int h = blockIdx.y;
    int rbase = (w & 1) * 32;
    int ntb = (w >> 1) * 4;
    float c[2][4][4] = {};
    const __half* wsrc = g_Wh + (size_t)h * NFEAT * NHID;

    auto issue = [&](int buf, int kc) {
#pragma unroll
        for (int p = 0; p < 2; p++) {
            int idx = p * 128 + t;
            int rr = idx >> 2, q = idx & 3;
            cpa16(Abase + buf * (64 * K1_AS) + rr * K1_AS + q * 16,
                  g_xh + (size_t)(i0 + rr) * NFEAT + kc + q * 8);
        }
#pragma unroll
        for (int p = 0; p < 2; p++) {
            int idx = p * 128 + t;
            int rr = idx >> 3, q = idx & 7;
            cpa16(Bbase + buf * (32 * K1_BS) + rr * K1_BS + q * 16,
                  wsrc + (size_t)(kc + rr) * NHID + q * 8);
        }
    };
    issue(0, 0); CP_COMMIT();

    for (int s = 0; s < 16; s++) {
        if (s < 15) { issue((s + 1) & 1, (s + 1) * 32); CP_COMMIT(); CP_WAIT1(); }
        else CP_WAIT0();
        __syncthreads();
        int buf = s & 1;
        uint32_t Ab2 = Abase + buf * (64 * K1_AS);
        uint32_t Bb2 = Bbase + buf * (32 * K1_BS);
        int g = l >> 3;
#pragma unroll
        for (int ks = 0; ks < 2; ks++) {
            uint32_t bq[4][2];
#pragma unroll
            for (int p = 0; p < 2; p++) {
                uint32_t addr = Bb2 + (ks * 16 + (g & 1) * 8 + (l & 7)) * K1_BS
                              + (ntb + p * 2 + (g >> 1)) * 16;
                LDSM_X4T(bq[p * 2][0], bq[p * 2][1], bq[p * 2 + 1][0], bq[p * 2 + 1][1], addr);
            }
#pragma unroll
            for (int rf = 0; rf < 2; rf++) {
                uint32_t a0, a1, a2, a3;
                uint32_t addr = Ab2 + (rbase + rf * 16 + (g & 1) * 8 + (l & 7)) * K1_AS
                              + (ks * 16 + (g >> 1) * 8) * 2;
                LDSM_X4(a0, a1, a2, a3, addr);
#pragma unroll
                for (int nt = 0; nt < 4; nt++)
                    mma16816(c[rf][nt], a0, a1, a2, a3, bq[nt][0], bq[nt][1]);
            }
        }
        __syncthreads();
    }
    __half* dst = g_Hf16 + (size_t)h * N * NHID;
#pragma unroll
    for (int rf = 0; rf < 2; rf++)
#pragma unroll
        for (int nt = 0; nt < 4; nt++) {
            int rl = rbase + rf * 16 + (l >> 2);
            int col = (ntb + nt) * 8 + 2 * (l & 3);
            uint32_t v01 = packh2(c[rf][nt][0], c[rf][nt][1]);
            uint32_t v23 = packh2(c[rf][nt][2], c[rf][nt][3]);
            *(uint32_t*)(dst + (size_t)(i0 + rl) * 64 + col) = v01;
            *(uint32_t*)(dst + (size_t)(i0 + rl + 8) * 64 + col) = v23;
            *(uint32_t*)(Hsm + rl * 64 + col) = v01;
            *(uint32_t*)(Hsm + (rl + 8) * 64 + col) = v23;
        }
    __syncthreads();

    float a1lo = As_[h * 128 + 2 * l], a1hi = As_[h * 128 + 2 * l + 1];
    float a2lo = As_[h * 128 + 64 + 2 * l], a2hi = As_[h * 128 + 64 + 2 * l + 1];
    for (int rr = 0; rr < 16; rr++) {
        int rl = w * 16 + rr;
        __half2 hv = ((__half2*)(Hsm + rl * 64))[l];
        float xl = __low2float(hv), xh = __high2float(hv);
        float s1p = xl * a1lo + xh * a1hi;
        float s2p = xl * a2lo + xh * a2hi;
#pragma unroll
        for (int o = 16; o > 0; o >>= 1) {
            s1p += __shfl_xor_sync(0xffffffffu, s1p, o);
            s2p += __shfl_xor_sync(0xffffffffu, s2p, o);
        }
        if (l == 0) {
            int idx = h * N + i0 + rl;
            g_E1h[idx]  = __float2half(expf(s1p));
            g_E1bh[idx] = __float2half(expf(0.2f * s1p));
            g_E2h[idx]  = __float2half(expf(s2p));
            g_E2bh[idx] = __float2half(expf(0.2f * s2p));
        }
    }
}

// ---------------- K3: layer-1 aggregation; 128 rows x 1 head x half-j per CTA ----------------
// grid (32 i-tiles, 16 = head*2+split), 2-buffer pipeline, partial num/den atomics.
#define K3_BBYTES 18432                    // per buf: 128j x 144B
#define K3_SCOFF (2 * K3_BBYTES)           // 36864
#define K3_SMEM (K3_SCOFF + 2 * 512)       // 37888
__global__ __launch_bounds__(256, 3) void k3_mma() {
    extern __shared__ __align__(16) char dsm[];
    uint32_t Bb = s2u(dsm);

    int t = threadIdx.x, w = t >> 5, l = t & 31;
    int i0 = blockIdx.x * 128;
    int h = blockIdx.y & 7;
    int jbeg = (blockIdx.y >> 3) * 2048;   // split 0/1
    int rq = w * 16 + (l >> 2);
    int jb = 2 * (l & 3);
    int g = l >> 3;

    // hoisted producer addressing
    int bj = t >> 3, bqv = t & 7;
    const char* src0 = (const char*)(g_Hf16 + ((size_t)h * N + jbeg + bj) * 64 + bqv * 8);
    uint32_t dst0 = Bb + bj * 144 + bqv * 16;
    int sc_type = (t >> 4) & 1, sc_jj = t & 15;
    const char* scsrc = (const char*)((sc_type ? g_E2bh : g_E2h) + (size_t)h * N + jbeg + sc_jj * 8);
    uint32_t scdst = Bb + K3_SCOFF + sc_type * 256 + sc_jj * 16;

    __half2 E1x2[2], E1bx2[2];
#pragma unroll
    for (int r = 0; r < 2; r++) {
        int gidx = h * N + i0 + rq + r * 8;
        E1x2[r] = __half2half2(g_E1h[gidx]);
        E1bx2[r] = __half2half2(g_E1bh[gidx]);
    }
    const uint4* adjp = (const uint4*)(g_adjbits + (size_t)(i0 + rq) * 128 + (jbeg >> 5));

    float c[8][4] = {}, cden[4] = {};
    uint32_t ones_b = (l < 4) ? 0x3C003C00u : 0u;

    auto issue = [&](int buf, int jo) {    // jo = local chunk offset within this split
        size_t so = (size_t)jo * 128;
        uint32_t bo = (uint32_t)buf * K3_BBYTES;
#pragma unroll
        for (int p = 0; p < 4; p++)
            cpa16(dst0 + bo + p * 4608, src0 + so + p * 4096);
        if (t < 32)
            cpa16(scdst + (uint32_t)buf * 512, scsrc + (size_t)jo * 2);
    };
    issue(0, 0); CP_COMMIT();

    for (int s = 0; s < 16; s++) {
        if (s < 15) { issue((s + 1) & 1, (s + 1) * 128); CP_COMMIT(); CP_WAIT1(); }
        else CP_WAIT0();
        __syncthreads();
        int buf = s & 1;

        const __half* scE2 = (const __half*)(dsm + K3_SCOFF + buf * 512);
        uint4 A0 = adjp[s];
        uint4 A1 = adjp[256 + s];
        uint32_t Bb2 = Bb + buf * K3_BBYTES;
#pragma unroll
        for (int ks = 0; ks < 8; ks++) {
            uint32_t sh = (ks & 1) * 16 + jb;
            uint32_t w0sel = (ks >> 1) == 0 ? A0.x : (ks >> 1) == 1 ? A0.y : (ks >> 1) == 2 ? A0.z : A0.w;
            uint32_t w1sel = (ks >> 1) == 0 ? A1.x : (ks >> 1) == 1 ? A1.y : (ks >> 1) == 2 ? A1.z : A1.w;
            uint32_t m0 = w0sel >> sh;
            uint32_t m1 = w1sel >> sh;
            uint32_t areg[4];
#pragma unroll
            for (int p = 0; p < 2; p++) {
                int j0 = ks * 16 + jb + p * 8;
                __half2 e2  = *(const __half2*)(scE2 + j0);
                __half2 e2b = *(const __half2*)(scE2 + 128 + j0);
                __half2 w0 = __hmax2(__hmul2(E1x2[0], e2), __hmul2(E1bx2[0], e2b));
                __half2 w1 = __hmax2(__hmul2(E1x2[1], e2), __hmul2(E1bx2[1], e2b));
                areg[p * 2]     = h2u(w0) & bits2mask((m0 >> (p * 8)) & 3u);
                areg[p * 2 + 1] = h2u(w1) & bits2mask((m1 >> (p * 8)) & 3u);
            }
#pragma unroll
            for (int p = 0; p < 4; p++) {
                uint32_t b0, b1, b2, b3;
                uint32_t addr = Bb2 + (ks * 16 + (g & 1) * 8 + (l & 7)) * 144
                              + (p * 2 + (g >> 1)) * 16;
                LDSM_X4T(b0, b1, b2, b3, addr);
                mma16816(c[p * 2],     areg[0], areg[1], areg[2], areg[3], b0, b1);
                mma16816(c[p * 2 + 1], areg[0], areg[1], areg[2], areg[3], b2, b3);
            }
            mma16816(cden, areg[0], areg[1], areg[2], areg[3], ones_b, ones_b);
        }
        __syncthreads();
    }

    float den0 = __shfl_sync(0xffffffffu, cden[0], l & ~3);
    float den1v = __shfl_sync(0xffffffffu, cden[2], l & ~3);
    if ((l & 3) == 0) {
        atomicAdd(&g_den1[h * N + i0 + rq], den0);
        atomicAdd(&g_den1[h * N + i0 + rq + 8], den1v);
    }
    float* np = g_num1 + ((size_t)h * N + i0) * 64;
#pragma unroll
    for (int nt = 0; nt < 8; nt++) {
        int col = nt * 8 + jb;
        atomicAdd(&np[(size_t)rq * 64 + col], c[nt][0]);
        atomicAdd(&np[(size_t)rq * 64 + col + 1], c[nt][1]);
        atomicAdd(&np[(size_t)(rq + 8) * 64 + col], c[nt][2]);
        atomicAdd(&np[(size_t)(rq + 8) * 64 + col + 1], c[nt][3]);
    }
}

// ---------------- K4: z = mean_h elu(num1/den1); h2 = z @ W_out; exp tables ----------------
__global__ __launch_bounds__(256) void k4_h2(const float* __restrict__ W_out,
                                             const float* __restrict__ a_out) {
    __shared__ float Wo[64 * 56];
    __shared__ float ao[112];
    __shared__ float zs[16 * 64];
    __shared__ float h2s[16 * 56];
    int t = threadIdx.x, w = t >> 5, l = t & 31;
    int i0 = blockIdx.x * 16;
    for (int idx = t; idx < 64 * 56; idx += 256) Wo[idx] = W_out[idx];
    if (t < 112) ao[t] = a_out[t];
    {
        int row = t >> 4, f4 = (t & 15) * 4;
        float4 acc = make_float4(0.f, 0.f, 0.f, 0.f);
#pragma unroll
        for (int hh = 0; hh < 8; hh++) {
            float invd = 1.f / g_den1[hh * N + i0 + row];
            float4 v = *(const float4*)&g_num1[((size_t)hh * N + i0 + row) * 64 + f4];
            float a;
            a = v.x * invd; a = (a > 0.f) ? a : expm1f(a); acc.x += a;
            a = v.y * invd; a = (a > 0.f) ? a : expm1f(a); acc.y += a;
            a = v.z * invd; a = (a > 0.f) ? a : expm1f(a); acc.z += a;
            a = v.w * invd; a = (a > 0.f) ? a : expm1f(a); acc.w += a;
        }
        acc.x *= 0.125f; acc.y *= 0.125f; acc.z *= 0.125f; acc.w *= 0.125f;
        *(float4*)&zs[row * 64 + f4] = acc;
    }
    __syncthreads();
    if (t < 224) {
        int i = t / 14, c4 = (t % 14) * 4;
        float ax = 0.f, ay = 0.f, az = 0.f, aw2 = 0.f;
#pragma unroll
        for (int k = 0; k < 64; k++) {
            float a = zs[i * 64 + k];
            float4 w4 = *(const float4*)&Wo[k * 56 + c4];
            ax = fmaf(a, w4.x, ax); ay = fmaf(a, w4.y, ay);
            az = fmaf(a, w4.z, az); aw2 = fmaf(a, w4.w, aw2);
        }
        h2s[i * 56 + c4] = ax; h2s[i * 56 + c4 + 1] = ay;
        h2s[i * 56 + c4 + 2] = az; h2s[i * 56 + c4 + 3] = aw2;
        *(uint32_t*)(g_H2f16 + (size_t)(i0 + i) * 64 + c4) = packh2(ax, ay);
        *(uint32_t*)(g_H2f16 + (size_t)(i0 + i) * 64 + c4 + 2) = packh2(az, aw2);
    }
    if (t < 16) g_H2f16[(size_t)(i0 + t) * 64 + 56] = __float2half(1.f);
    if (t >= 32 && t < 144) {
        int u = t - 32;
        g_H2f16[(size_t)(i0 + u / 7) * 64 + 57 + (u % 7)] = __float2half(0.f);
    }
    __syncthreads();
#pragma unroll
    for (int rr = 0; rr < 2; rr++) {
        int row = w * 2 + rr;
        float v1 = h2s[row * 56 + l];
        float v2 = (l < 24) ? h2s[row * 56 + 32 + l] : 0.f;
        float s1 = v1 * ao[l] + ((l < 24) ? v2 * ao[32 + l] : 0.f);
        float s2 = v1 * ao[56 + l] + ((l < 24) ? v2 * ao[88 + l] : 0.f);
#pragma unroll
        for (int o = 16; o > 0; o >>= 1) {
            s1 += __shfl_xor_sync(0xffffffffu, s1, o);
            s2 += __shfl_xor_sync(0xffffffffu, s2, o);
        }
        if (l == 0) {
            int i = i0 + row;
            g_E1oh[i]  = __float2half(expf(s1));
            g_E1boh[i] = __float2half(expf(0.2f * s1));
            g_E2oh[i]  = __float2half(expf(s2));
            g_E2boh[i] = __float2half(expf(0.2f * s2));
        }
    }
}

// ---------------- K5: layer-2 aggregation; grid (32,16), 256 j per CTA; den = col 56 ----------------
#define K5_BBYTES 18432
#define K5_SCOFF (2 * K5_BBYTES)           // 36864
#define K5_SMEM (K5_SCOFF + 2 * 512)       // 37888
__global__ __launch_bounds__(256, 3) void k5_mma() {
    extern __shared__ __align__(16) char dsm[];
    uint32_t Bb = s2u(dsm);
    int t = threadIdx.x, w = t >> 5, l = t & 31;
    int i0 = blockIdx.x * 128, jbeg = blockIdx.y * 256;
    int rq = w * 16 + (l >> 2);
    int jb = 2 * (l & 3);
    int g = l >> 3;

    int bj = t >> 3, bqv = t & 7;
    const char* src0 = (const char*)(g_H2f16 + (size_t)(jbeg + bj) * 64 + bqv * 8);
    uint32_t dst0 = Bb + bj * 144 + bqv * 16;
    int sc_type = (t >> 4) & 1, sc_jj = t & 15;
    const char* scsrc = (const char*)((sc_type ? g_E2boh : g_E2oh) + jbeg + sc_jj * 8);
    uint32_t scdst = Bb + K5_SCOFF + sc_type * 256 + sc_jj * 16;

    __half2 E1x2[2], E1bx2[2];
#pragma unroll
    for (int r = 0; r < 2; r++) {
        int gidx = i0 + rq + r * 8;
        E1x2[r] = __half2half2(g_E1oh[gidx]);
        E1bx2[r] = __half2half2(g_E1boh[gidx]);
    }
    const uint4* adjp = (const uint4*)(g_adjbits + (size_t)(i0 + rq) * 128 + (jbeg >> 5));

    float c[8][4] = {};

    auto issue = [&](int buf, int jo) {
        size_t so = (size_t)jo * 128;
        uint32_t bo = (uint32_t)buf * K5_BBYTES;
#pragma unroll
        for (int p = 0; p < 4; p++)
            cpa16(dst0 + bo + p * 4608, src0 + so + p * 4096);
        if (t < 32)
            cpa16(scdst + (uint32_t)buf * 512, scsrc + (size_t)jo * 2);
    };
    issue(0, 0); CP_COMMIT();

    for (int s = 0; s < 2; s++) {
        if (s < 1) { issue(1, 128); CP_COMMIT(); CP_WAIT1(); }
        else CP_WAIT0();
        __syncthreads();
        int buf = s & 1;

        const __half* scE2 = (const __half*)(dsm + K5_SCOFF + buf * 512);
        uint4 A0 = adjp[s];
        uint4 A1 = adjp[256 + s];
        uint32_t Bb2 = Bb + buf * K5_BBYTES;
#pragma unroll
        for (int ks = 0; ks < 8; ks++) {
            uint32_t sh = (ks & 1) * 16 + jb;
            uint32_t w0sel = (ks >> 1) == 0 ? A0.x : (ks >> 1) == 1 ? A0.y : (ks >> 1) == 2 ? A0.z : A0.w;
            uint32_t w1sel = (ks >> 1) == 0 ? A1.x : (ks >> 1) == 1 ? A1.y : (ks >> 1) == 2 ? A1.z : A1.w;
            uint32_t m0 = w0sel >> sh;
            uint32_t m1 = w1sel >> sh;
            uint32_t areg[4];
#pragma unroll
            for (int p = 0; p < 2; p++) {
                int j0 = ks * 16 + jb + p * 8;
                __half2 e2  = *(const __half2*)(scE2 + j0);
                __half2 e2b = *(const __half2*)(scE2 + 128 + j0);
                __half2 w0 = __hmax2(__hmul2(E1x2[0], e2), __hmul2(E1bx2[0], e2b));
                __half2 w1 = __hmax2(__hmul2(E1x2[1], e2), __hmul2(E1bx2[1], e2b));
                areg[p * 2]     = h2u(w0) & bits2mask((m0 >> (p * 8)) & 3u);
                areg[p * 2 + 1] = h2u(w1) & bits2mask((m1 >> (p * 8)) & 3u);
            }
#pragma unroll
            for (int p = 0; p < 4; p++) {
                uint32_t b0, b1, b2, b3;
                uint32_t addr = Bb2 + (ks * 16 + (g & 1) * 8 + (l & 7)) * 144
                              + (p * 2 + (g >> 1)) * 16;
                LDSM_X4T(b0, b1, b2, b3, addr);
                mma16816(c[p * 2],     areg[0], areg[1], areg[2], areg[3], b0, b1);
                mma16816(c[p * 2 + 1], areg[0], areg[1], areg[2], areg[3], b2, b3);
            }
        }
        __syncthreads();
    }

    float den0 = __shfl_sync(0xffffffffu, c[7][0], l & ~3);
    float den1 = __shfl_sync(0xffffffffu, c[7][2], l & ~3);
    if ((l & 3) == 0) {
        atomicAdd(&g_den2[i0 + rq], den0);
        atomicAdd(&g_den2[i0 + rq + 8], den1);
    }
#pragma unroll
    for (int nt = 0; nt < 7; nt++) {
        int col = nt * 8 + jb;
        atomicAdd(&g_num2[(size_t)(i0 + rq) * NOUT + col], c[nt][0]);
        atomicAdd(&g_num2[(size_t)(i0 + rq) * NOUT + col + 1], c[nt][1]);
        atomicAdd(&g_num2[(size_t)(i0 + rq + 8) * NOUT + col], c[nt][2]);
        atomicAdd(&g_num2[(size_t)(i0 + rq + 8) * NOUT + col + 1], c[nt][3]);
    }
}

// ---------------- K6: out = softmax(elu(num2/den2)) ----------------
__global__ __launch_bounds__(256) void k6_final(float* __restrict__ out) {
    int wid = (blockIdx.x * 256 + threadIdx.x) >> 5;
    int lane = threadIdx.x & 31;
    if (wid >= N) return;
    float invd = 1.0f / g_den2[wid];
    float v1 = g_num2[(size_t)wid * NOUT + lane] * invd;
    v1 = (v1 > 0.f) ? v1 : expm1f(v1);
    float v2 = -1e30f;
    if (lane < 24) {
        v2 = g_num2[(size_t)wid * NOUT + 32 + lane] * invd;
        v2 = (v2 > 0.f) ? v2 : expm1f(v2);
    }
    float m = fmaxf(v1, v2);
#pragma unroll
    for (int o = 16; o > 0; o >>= 1) m = fmaxf(m, __shfl_xor_sync(0xffffffffu, m, o));
    float e1 = expf(v1 - m);
    float e2 = (lane < 24) ? expf(v2 - m) : 0.f;
    float s = e1 + e2;
#pragma unroll
    for (int o = 16; o > 0; o >>= 1) s += __shfl_xor_sync(0xffffffffu, s, o);
    float invs = 1.0f / s;
    out[(size_t)wid * NOUT + lane] = e1 * invs;
    if (lane < 24) out[(size_t)wid * NOUT + 32 + lane] = e2 * invs;
}

// ---------------- launch ----------------
extern "C" void kernel_launch(void* const* d_in, const int* in_sizes, int n_in,
                              void* d_out, int out_size) {
    (void)in_sizes; (void)n_in; (void)out_size;
    const float* x     = (const float*)d_in[0];
    const int*   adj   = (const int*)d_in[1];
    const float* Ws    = (const float*)d_in[2];
    const float* As_   = (const float*)d_in[3];
    const float* W_out = (const float*)d_in[4];
    const float* a_out = (const float*)d_in[5];
    float* out = (float*)d_out;

    cudaFuncSetAttribute(k3_mma, cudaFuncAttributeMaxDynamicSharedMemorySize, K3_SMEM);
    cudaFuncSetAttribute(k5_mma, cudaFuncAttributeMaxDynamicSharedMemorySize, K5_SMEM);

    kA_init<<<2048, 256>>>(x, Ws, adj);
    k1_mma<<<dim3(64, 8), 128>>>(As_);
    k_nop<<<1, 32>>>();
    k3_mma<<<dim3(32, 16), 256, K3_SMEM>>>();
    k4_h2<<<256, 256>>>(W_out, a_out);
    k5_mma<<<dim3(32, 16), 256, K5_SMEM>>>();
    k6_final<<<512, 256>>>(out);
}

// round 14
// speedup vs baseline: 1.6493x; 1.6493x over previous
#include <cuda_runtime.h>
#include <cuda_fp16.h>
#include <math.h>
#include <stdint.h>

#define N 4096
#define NHEADS 8
#define NHID 64
#define NFEAT 512
#define NOUT 56

// ---------------- device scratch ----------------
__device__ __half g_xh[(size_t)N * NFEAT];
__device__ __half g_Wh[(size_t)NHEADS * NFEAT * NHID];
__device__ __half g_Hf16[(size_t)NHEADS * N * NHID];
__device__ uint32_t g_adjbits[(size_t)N * 128];
__device__ __half g_E1h[NHEADS * N], g_E1bh[NHEADS * N];
__device__ __half g_E2h[NHEADS * N], g_E2bh[NHEADS * N];
__device__ float g_Z[N * NHID];
__device__ __half g_H2f16[(size_t)N * 64];   // col 56 = 1.0 (den trick), 57-63 = 0
__device__ __half g_E1oh[N], g_E1boh[N], g_E2oh[N], g_E2boh[N];
__device__ float g_num2[N * NOUT];
__device__ float g_den2[N];

// ---------------- helpers ----------------
__device__ __forceinline__ uint32_t s2u(const void* p) {
    uint32_t a;
    asm("{ .reg .u64 t; cvta.to.shared.u64 t, %1; cvt.u32.u64 %0, t; }" : "=r"(a) : "l"(p));
    return a;
}
#define LDSM_X4(r0, r1, r2, r3, a) \
    asm volatile("ldmatrix.sync.aligned.m8n8.x4.shared.b16 {%0,%1,%2,%3}, [%4];" \
                 : "=r"(r0), "=r"(r1), "=r"(r2), "=r"(r3) : "r"(a))
#define LDSM_X4T(r0, r1, r2, r3, a) \
    asm volatile("ldmatrix.sync.aligned.m8n8.x4.trans.shared.b16 {%0,%1,%2,%3}, [%4];" \
                 : "=r"(r0), "=r"(r1), "=r"(r2), "=r"(r3) : "r"(a))

__device__ __forceinline__ void mma16816(float* c, uint32_t a0, uint32_t a1, uint32_t a2,
                                         uint32_t a3, uint32_t b0, uint32_t b1) {
    asm volatile(
        "mma.sync.aligned.m16n8k16.row.col.f32.f16.f16.f32 "
        "{%0,%1,%2,%3}, {%4,%5,%6,%7}, {%8,%9}, {%0,%1,%2,%3};"
        : "+f"(c[0]), "+f"(c[1]), "+f"(c[2]), "+f"(c[3])
        : "r"(a0), "r"(a1), "r"(a2), "r"(a3), "r"(b0), "r"(b1));
}
__device__ __forceinline__ uint32_t packh2(float lo, float hi) {
    __half2 h = __floats2half2_rn(lo, hi);
    return *(uint32_t*)&h;
}
__device__ __forceinline__ uint32_t h2u(__half2 h) { return *(uint32_t*)&h; }
__device__ __forceinline__ uint32_t bits2mask(uint32_t b) {
    return ((b & 1u) ? 0x0000FFFFu : 0u) | ((b & 2u) ? 0xFFFF0000u : 0u);
}
__device__ __forceinline__ void cpa16(uint32_t dst, const void* src) {
    asm volatile("cp.async.cg.shared.global [%0], [%1], 16;" :: "r"(dst), "l"(src));
}
#define CP_COMMIT() asm volatile("cp.async.commit_group;")
#define CP_WAIT1()  asm volatile("cp.async.wait_group 1;")
#define CP_WAIT0()  asm volatile("cp.async.wait_group 0;")

// ---------------- KA: merged init (zero + fp16 convert + adj bitmask) ----------------
__global__ __launch_bounds__(256) void kA_init(const float* __restrict__ x,
                                               const float* __restrict__ Ws,
                                               const int* __restrict__ adj) {
    int t = threadIdx.x;
    int gid = blockIdx.x * 256 + t;
    int stride = gridDim.x * 256;
    int w = gid >> 5, lane = t & 31;
    int row = w >> 2, quarter = w & 3;
    const int4* src = (const int4*)(adj + (size_t)row * N + quarter * 1024);
    uint32_t* dstw = g_adjbits + (size_t)row * 128 + quarter * 32;
#pragma unroll
    for (int it = 0; it < 8; it++) {
        int4 v = src[it * 32 + lane];
        uint32_t nib = (uint32_t)(v.x > 0) | ((uint32_t)(v.y > 0) << 1)
                     | ((uint32_t)(v.z > 0) << 2) | ((uint32_t)(v.w > 0) << 3);
        uint32_t word = nib << (4 * (lane & 7));
        word |= __shfl_xor_sync(0xffffffffu, word, 1);
        word |= __shfl_xor_sync(0xffffffffu, word, 2);
        word |= __shfl_xor_sync(0xffffffffu, word, 4);
        if ((lane & 7) == 0) dstw[it * 4 + (lane >> 3)] = word;
    }
    for (int i = gid; i < N * NFEAT / 2; i += stride) {
        float2 v = ((const float2*)x)[i];
        ((__half2*)g_xh)[i] = __floats2half2_rn(v.x, v.y);
    }
    for (int i = gid; i < NHEADS * NFEAT * NHID / 2; i += stride) {
        float2 v = ((const float2*)Ws)[i];
        ((__half2*)g_Wh)[i] = __floats2half2_rn(v.x, v.y);
    }
    for (int i = gid; i < N * NHID; i += stride) g_Z[i] = 0.f;
    for (int i = gid; i < N * NOUT; i += stride) g_num2[i] = 0.f;
    for (int i = gid; i < N; i += stride) g_den2[i] = 0.f;
}

// ---------------- dummy: keeps k3 in the profiler's capture slot ----------------
__global__ void k_nop() {}

// ---------------- K1: H = x @ Ws, 64x64 tile, 128 threads, fused exp epilogue ----------------
#define K1_AS 80
#define K1_BS 144
__global__ __launch_bounds__(128) void k1_mma(const float* __restrict__ As_) {
    __shared__ __align__(16) char Asm[2][64 * K1_AS];
    __shared__ __align__(16) char Bsm[2][32 * K1_BS];
    __shared__ __align__(16) __half Hsm[64 * 64];
    uint32_t Abase = s2u(Asm), Bbase = s2u(Bsm);
    int t = threadIdx.x, w = t >> 5, l = t & 31;
    int i0 = blockIdx.x * 64;
    int h = blockIdx.y;
    int rbase = (w & 1) * 32;
    int ntb = (w >> 1) * 4;
    float c[2][4][4] = {};
    const __half* wsrc = g_Wh + (size_t)h * NFEAT * NHID;

    auto issue = [&](int buf, int kc) {
#pragma unroll
        for (int p = 0; p < 2; p++) {
            int idx = p * 128 + t;
            int rr = idx >> 2, q = idx & 3;
            cpa16(Abase + buf * (64 * K1_AS) + rr * K1_AS + q * 16,
                  g_xh + (size_t)(i0 + rr) * NFEAT + kc + q * 8);
        }
#pragma unroll
        for (int p = 0; p < 2; p++) {
            int idx = p * 128 + t;
            int rr = idx >> 3, q = idx & 7;
            cpa16(Bbase + buf * (32 * K1_BS) + rr * K1_BS + q * 16,
                  wsrc + (size_t)(kc + rr) * NHID + q * 8);
        }
    };
    issue(0, 0); CP_COMMIT();

    for (int s = 0; s < 16; s++) {
        if (s < 15) { issue((s + 1) & 1, (s + 1) * 32); CP_COMMIT(); CP_WAIT1(); }
        else CP_WAIT0();
        __syncthreads();
        int buf = s & 1;
        uint32_t Ab2 = Abase + buf * (64 * K1_AS);
        uint32_t Bb2 = Bbase + buf * (32 * K1_BS);
        int g = l >> 3;
#pragma unroll
        for (int ks = 0; ks < 2; ks++) {
            uint32_t bq[4][2];
#pragma unroll
            for (int p = 0; p < 2; p++) {
                uint32_t addr = Bb2 + (ks * 16 + (g & 1) * 8 + (l & 7)) * K1_BS
                              + (ntb + p * 2 + (g >> 1)) * 16;
                LDSM_X4T(bq[p * 2][0], bq[p * 2][1], bq[p * 2 + 1][0], bq[p * 2 + 1][1], addr);
            }
#pragma unroll
            for (int rf = 0; rf < 2; rf++) {
                uint32_t a0, a1, a2, a3;
                uint32_t addr = Ab2 + (rbase + rf * 16 + (g & 1) * 8 + (l & 7)) * K1_AS
                              + (ks * 16 + (g >> 1) * 8) * 2;
                LDSM_X4(a0, a1, a2, a3, addr);
#pragma unroll
                for (int nt = 0; nt < 4; nt++)
                    mma16816(c[rf][nt], a0, a1, a2, a3, bq[nt][0], bq[nt][1]);
            }
        }
        __syncthreads();
    }
    __half* dst = g_Hf16 + (size_t)h * N * NHID;
#pragma unroll
    for (int rf = 0; rf < 2; rf++)
#pragma unroll
        for (int nt = 0; nt < 4; nt++) {
            int rl = rbase + rf * 16 + (l >> 2);
            int col = (ntb + nt) * 8 + 2 * (l & 3);
            uint32_t v01 = packh2(c[rf][nt][0], c[rf][nt][1]);
            uint32_t v23 = packh2(c[rf][nt][2], c[rf][nt][3]);
            *(uint32_t*)(dst + (size_t)(i0 + rl) * 64 + col) = v01;
            *(uint32_t*)(dst + (size_t)(i0 + rl + 8) * 64 + col) = v23;
            *(uint32_t*)(Hsm + rl * 64 + col) = v01;
            *(uint32_t*)(Hsm + (rl + 8) * 64 + col) = v23;
        }
    __syncthreads();

    float a1lo = As_[h * 128 + 2 * l], a1hi = As_[h * 128 + 2 * l + 1];
    float a2lo = As_[h * 128 + 64 + 2 * l], a2hi = As_[h * 128 + 64 + 2 * l + 1];
    for (int rr = 0; rr < 16; rr++) {
        int rl = w * 16 + rr;
        __half2 hv = ((__half2*)(Hsm + rl * 64))[l];
        float xl = __low2float(hv), xh = __high2float(hv);
        float s1p = xl * a1lo + xh * a1hi;
        float s2p = xl * a2lo + xh * a2hi;
#pragma unroll
        for (int o = 16; o > 0; o >>= 1) {
            s1p += __shfl_xor_sync(0xffffffffu, s1p, o);
            s2p += __shfl_xor_sync(0xffffffffu, s2p, o);
        }
        if (l == 0) {
            int idx = h * N + i0 + rl;
            g_E1h[idx]  = __float2half(expf(s1p));
            g_E1bh[idx] = __float2half(expf(0.2f * s1p));
            g_E2h[idx]  = __float2half(expf(s2p));
            g_E2bh[idx] = __float2half(expf(0.2f * s2p));
        }
    }
}

// ---------------- K3: layer-1 aggregation; 128 rows x 1 head per CTA (R11 config + adj prefetch) ----------------
#define K3_BBYTES 18432                    // per buf: 128j x 144B
#define K3_SCOFF (3 * K3_BBYTES)           // 55296
#define K3_SMEM (K3_SCOFF + 3 * 512)       // 56832
__global__ __launch_bounds__(256, 2) void k3_mma() {
    extern __shared__ __align__(16) char dsm[];
    uint32_t Bb = s2u(dsm);

    int t = threadIdx.x, w = t >> 5, l = t & 31;
    int i0 = blockIdx.x * 128;
    int h = blockIdx.y;
    int rq = w * 16 + (l >> 2);
    int jb = 2 * (l & 3);
    int g = l >> 3;

    // hoisted producer addressing
    int bj = t >> 3, bqv = t & 7;
    const char* src0 = (const char*)(g_Hf16 + ((size_t)h * N + bj) * 64 + bqv * 8);
    uint32_t dst0 = Bb + bj * 144 + bqv * 16;
    int sc_type = (t >> 4) & 1, sc_jj = t & 15;
    const char* scsrc = (const char*)((sc_type ? g_E2bh : g_E2h) + (size_t)h * N + sc_jj * 8);
    uint32_t scdst = Bb + K3_SCOFF + sc_type * 256 + sc_jj * 16;

    __half2 E1x2[2], E1bx2[2];
#pragma unroll
    for (int r = 0; r < 2; r++) {
        int gidx = h * N + i0 + rq + r * 8;
        E1x2[r] = __half2half2(g_E1h[gidx]);
        E1bx2[r] = __half2half2(g_E1bh[gidx]);
    }
    const uint4* adjp0 = (const uint4*)(g_adjbits + (size_t)(i0 + rq) * 128);
    const uint4* adjp1 = (const uint4*)(g_adjbits + (size_t)(i0 + rq + 8) * 128);

    float c[8][4] = {}, cdenA[4] = {}, cdenB[4] = {};
    uint32_t ones_b = (l < 4) ? 0x3C003C00u : 0u;

    auto issue = [&](int buf, int jc) {
        size_t so = (size_t)jc * 128;           // jc rows * 64 halves * 2B
        uint32_t bo = (uint32_t)buf * K3_BBYTES;
#pragma unroll
        for (int p = 0; p < 4; p++)
            cpa16(dst0 + bo + p * 4608, src0 + so + p * 4096);
        if (t < 32)
            cpa16(scdst + (uint32_t)buf * 512, scsrc + (size_t)jc * 2);
    };
    issue(0, 0);   CP_COMMIT();
    issue(1, 128); CP_COMMIT();

    // prefetch adj for chunk 0
    uint4 P0 = adjp0[0];
    uint4 P1 = adjp1[0];

    for (int s = 0; s < 32; s++) {
        int buf = s - (s / 3) * 3;
        CP_WAIT1();
        __syncthreads();
        if (s < 30) issue((s + 2) - ((s + 2) / 3) * 3, s * 128 + 256);
        CP_COMMIT();

        uint4 A0 = P0, A1 = P1;
        if (s < 31) { P0 = adjp0[s + 1]; P1 = adjp1[s + 1]; }

        const __half* scE2 = (const __half*)(dsm + K3_SCOFF + buf * 512);
        uint32_t aw0[4] = {A0.x, A0.y, A0.z, A0.w};
        uint32_t aw1[4] = {A1.x, A1.y, A1.z, A1.w};
        uint32_t Bb2 = Bb + buf * K3_BBYTES;
#pragma unroll
        for (int ks = 0; ks < 8; ks++) {
            uint32_t sh = (ks & 1) * 16 + jb;
            uint32_t m0 = aw0[ks >> 1] >> sh;
            uint32_t m1 = aw1[ks >> 1] >> sh;
            uint32_t areg[4];
#pragma unroll
            for (int p = 0; p < 2; p++) {
                int j0 = ks * 16 + jb + p * 8;
                __half2 e2  = *(const __half2*)(scE2 + j0);
                __half2 e2b = *(const __half2*)(scE2 + 128 + j0);
                __half2 w0 = __hmax2(__hmul2(E1x2[0], e2), __hmul2(E1bx2[0], e2b));
                __half2 w1 = __hmax2(__hmul2(E1x2[1], e2), __hmul2(E1bx2[1], e2b));
                areg[p * 2]     = h2u(w0) & bits2mask((m0 >> (p * 8)) & 3u);
                areg[p * 2 + 1] = h2u(w1) & bits2mask((m1 >> (p * 8)) & 3u);
            }
#pragma unroll
            for (int p = 0; p < 4; p++) {
                uint32_t b0, b1, b2, b3;
                uint32_t addr = Bb2 + (ks * 16 + (g & 1) * 8 + (l & 7)) * 144
                              + (p * 2 + (g >> 1)) * 16;
                LDSM_X4T(b0, b1, b2, b3, addr);
                mma16816(c[p * 2],     areg[0], areg[1], areg[2], areg[3], b0, b1);
                mma16816(c[p * 2 + 1], areg[0], areg[1], areg[2], areg[3], b2, b3);
            }
            if (ks & 1) mma16816(cdenB, areg[0], areg[1], areg[2], areg[3], ones_b, ones_b);
            else        mma16816(cdenA, areg[0], areg[1], areg[2], areg[3], ones_b, ones_b);
        }
    }

    float den0 = __shfl_sync(0xffffffffu, cdenA[0] + cdenB[0], l & ~3);
    float den1 = __shfl_sync(0xffffffffu, cdenA[2] + cdenB[2], l & ~3);
    float inv0 = 1.f / den0, inv1 = 1.f / den1;
#pragma unroll
    for (int nt = 0; nt < 8; nt++) {
        int col = nt * 8 + jb;
        float va, vb;
        va = c[nt][0] * inv0; va = (va > 0.f) ? va : expm1f(va);
        vb = c[nt][1] * inv0; vb = (vb > 0.f) ? vb : expm1f(vb);
        atomicAdd(&g_Z[(size_t)(i0 + rq) * 64 + col], 0.125f * va);
        atomicAdd(&g_Z[(size_t)(i0 + rq) * 64 + col + 1], 0.125f * vb);
        va = c[nt][2] * inv1; va = (va > 0.f) ? va : expm1f(va);
        vb = c[nt][3] * inv1; vb = (vb > 0.f) ? vb : expm1f(vb);
        atomicAdd(&g_Z[(size_t)(i0 + rq + 8) * 64 + col], 0.125f * va);
        atomicAdd(&g_Z[(size_t)(i0 + rq + 8) * 64 + col + 1], 0.125f * vb);
    }
}

// ---------------- K4: h2 = z @ W_out; float4 cols per thread; pad col56=1 ----------------
__global__ __launch_bounds__(256) void k4_h2(const float* __restrict__ W_out,
                                             const float* __restrict__ a_out) {
    __shared__ float Wo[64 * 56];
    __shared__ float ao[112];
    __shared__ float zs[16 * 64];
    __shared__ float h2s[16 * 56];
    int t = threadIdx.x, w = t >> 5, l = t & 31;
    int i0 = blockIdx.x * 16;
    for (int idx = t; idx < 64 * 56; idx += 256) Wo[idx] = W_out[idx];
    if (t < 112) ao[t] = a_out[t];
    *(float4*)&zs[t * 4] = *(const float4*)&g_Z[(size_t)(i0 + (t >> 4)) * 64 + (t & 15) * 4];
    __syncthreads();
    if (t < 224) {
        int i = t / 14, c4 = (t % 14) * 4;
        float ax = 0.f, ay = 0.f, az = 0.f, aw2 = 0.f;
#pragma unroll
        for (int k = 0; k < 64; k++) {
            float a = zs[i * 64 + k];
            float4 w4 = *(const float4*)&Wo[k * 56 + c4];
            ax = fmaf(a, w4.x, ax); ay = fmaf(a, w4.y, ay);
            az = fmaf(a, w4.z, az); aw2 = fmaf(a, w4.w, aw2);
        }
        h2s[i * 56 + c4] = ax; h2s[i * 56 + c4 + 1] = ay;
        h2s[i * 56 + c4 + 2] = az; h2s[i * 56 + c4 + 3] = aw2;
        *(uint32_t*)(g_H2f16 + (size_t)(i0 + i) * 64 + c4) = packh2(ax, ay);
        *(uint32_t*)(g_H2f16 + (size_t)(i0 + i) * 64 + c4 + 2) = packh2(az, aw2);
    }
    if (t < 16) g_H2f16[(size_t)(i0 + t) * 64 + 56] = __float2half(1.f);
    if (t >= 32 && t < 144) {
        int u = t - 32;
        g_H2f16[(size_t)(i0 + u / 7) * 64 + 57 + (u % 7)] = __float2half(0.f);
    }
    __syncthreads();
#pragma unroll
    for (int rr = 0; rr < 2; rr++) {
        int row = w * 2 + rr;
        float v1 = h2s[row * 56 + l];
        float v2 = (l < 24) ? h2s[row * 56 + 32 + l] : 0.f;
        float s1 = v1 * ao[l] + ((l < 24) ? v2 * ao[32 + l] : 0.f);
        float s2 = v1 * ao[56 + l] + ((l < 24) ? v2 * ao[88 + l] : 0.f);
#pragma unroll
        for (int o = 16; o > 0; o >>= 1) {
            s1 += __shfl_xor_sync(0xffffffffu, s1, o);
            s2 += __shfl_xor_sync(0xffffffffu, s2, o);
        }
        if (l == 0) {
            int i = i0 + row;
            g_E1oh[i]  = __float2half(expf(s1));
            g_E1boh[i] = __float2half(expf(0.2f * s1));
            g_E2oh[i]  = __float2half(expf(s2));
            g_E2boh[i] = __float2half(expf(0.2f * s2));
        }
    }
}

// ---------------- K5: layer-2 aggregation; chunk=128, hoisted addrs; den = col 56 ----------------
#define K5_BBYTES 18432
#define K5_SCOFF (3 * K5_BBYTES)           // 55296
#define K5_SMEM (K5_SCOFF + 3 * 512)       // 56832
__global__ __launch_bounds__(256, 2) void k5_mma() {
    extern __shared__ __align__(16) char dsm[];
    uint32_t Bb = s2u(dsm);
    int t = threadIdx.x, w = t >> 5, l = t & 31;
    int i0 = blockIdx.x * 128, jbeg = blockIdx.y * 512;
    int rq = w * 16 + (l >> 2);
    int jb = 2 * (l & 3);
    int g = l >> 3;

    int bj = t >> 3, bqv = t & 7;
    const char* src0 = (const char*)(g_H2f16 + (size_t)bj * 64 + bqv * 8);
    uint32_t dst0 = Bb + bj * 144 + bqv * 16;
    int sc_type = (t >> 4) & 1, sc_jj = t & 15;
    const char* scsrc = (const char*)((sc_type ? g_E2boh : g_E2oh) + sc_jj * 8);
    uint32_t scdst = Bb + K5_SCOFF + sc_type * 256 + sc_jj * 16;

    __half2 E1x2[2], E1bx2[2];
#pragma unroll
    for (int r = 0; r < 2; r++) {
        int gidx = i0 + rq + r * 8;
        E1x2[r] = __half2half2(g_E1oh[gidx]);
        E1bx2[r] = __half2half2(g_E1boh[gidx]);
    }
    const uint4* adjp0 = (const uint4*)(g_adjbits + (size_t)(i0 + rq) * 128 + (jbeg >> 5));
    const uint4* adjp1 = (const uint4*)(g_adjbits + (size_t)(i0 + rq + 8) * 128 + (jbeg >> 5));

    float c[8][4] = {};

    auto issue = [&](int buf, int jc) {
        size_t so = (size_t)jc * 128;
        uint32_t bo = (uint32_t)buf * K5_BBYTES;
#pragma unroll
        for (int p = 0; p < 4; p++)
            cpa16(dst0 + bo + p * 4608, src0 + so + p * 4096);
        if (t < 32)
            cpa16(scdst + (uint32_t)buf * 512, scsrc + (size_t)jc * 2);
    };
    issue(0, jbeg);       CP_COMMIT();
    issue(1, jbeg + 128); CP_COMMIT();

    for (int s = 0; s < 4; s++) {
        int buf = s - (s / 3) * 3;
        CP_WAIT1();
        __syncthreads();
        if (s < 2) issue((s + 2) % 3, jbeg + s * 128 + 256);
        CP_COMMIT();

        const __half* scE2 = (const __half*)(dsm + K5_SCOFF + buf * 512);
        uint4 A0 = adjp0[s];
        uint4 A1 = adjp1[s];
        uint32_t aw0[4] = {A0.x, A0.y, A0.z, A0.w};
        uint32_t aw1[4] = {A1.x, A1.y, A1.z, A1.w};
        uint32_t Bb2 = Bb + buf * K5_BBYTES;
#pragma unroll
        for (int ks = 0; ks < 8; ks++) {
            uint32_t sh = (ks & 1) * 16 + jb;
            uint32_t m0 = aw0[ks >> 1] >> sh;
            uint32_t m1 = aw1[ks >> 1] >> sh;
            uint32_t areg[4];
#pragma unroll
            for (int p = 0; p < 2; p++) {
                int j0 = ks * 16 + jb + p * 8;
                __half2 e2  = *(const __half2*)(scE2 + j0);
                __half2 e2b = *(const __half2*)(scE2 + 128 + j0);
                __half2 w0 = __hmax2(__hmul2(E1x2[0], e2), __hmul2(E1bx2[0], e2b));
                __half2 w1 = __hmax2(__hmul2(E1x2[1], e2), __hmul2(E1bx2[1], e2b));
                areg[p * 2]     = h2u(w0) & bits2mask((m0 >> (p * 8)) & 3u);
                areg[p * 2 + 1] = h2u(w1) & bits2mask((m1 >> (p * 8)) & 3u);
            }
#pragma unroll
            for (int p = 0; p < 4; p++) {
                uint32_t b0, b1, b2, b3;
                uint32_t addr = Bb2 + (ks * 16 + (g & 1) * 8 + (l & 7)) * 144
                              + (p * 2 + (g >> 1)) * 16;
                LDSM_X4T(b0, b1, b2, b3, addr);
                mma16816(c[p * 2],     areg[0], areg[1], areg[2], areg[3], b0, b1);
                mma16816(c[p * 2 + 1], areg[0], areg[1], areg[2], areg[3], b2, b3);
            }
        }
    }

    float den0 = __shfl_sync(0xffffffffu, c[7][0], l & ~3);
    float den1 = __shfl_sync(0xffffffffu, c[7][2], l & ~3);
    if ((l & 3) == 0) {
        atomicAdd(&g_den2[i0 + rq], den0);
        atomicAdd(&g_den2[i0 + rq + 8], den1);
    }
#pragma unroll
    for (int nt = 0; nt < 7; nt++) {
        int col = nt * 8 + jb;
        atomicAdd(&g_num2[(size_t)(i0 + rq) * NOUT + col], c[nt][0]);
        atomicAdd(&g_num2[(size_t)(i0 + rq) * NOUT + col + 1], c[nt][1]);
        atomicAdd(&g_num2[(size_t)(i0 + rq + 8) * NOUT + col], c[nt][2]);
        atomicAdd(&g_num2[(size_t)(i0 + rq + 8) * NOUT + col + 1], c[nt][3]);
    }
}

// ---------------- K6: out = softmax(elu(num2/den2)) ----------------
__global__ __launch_bounds__(256) void k6_final(float* __restrict__ out) {
    int wid = (blockIdx.x * 256 + threadIdx.x) >> 5;
    int lane = threadIdx.x & 31;
    if (wid >= N) return;
    float invd = 1.0f / g_den2[wid];
    float v1 = g_num2[(size_t)wid * NOUT + lane] * invd;
    v1 = (v1 > 0.f) ? v1 : expm1f(v1);
    float v2 = -1e30f;
    if (lane < 24) {
        v2 = g_num2[(size_t)wid * NOUT + 32 + lane] * invd;
        v2 = (v2 > 0.f) ? v2 : expm1f(v2);
    }
    float m = fmaxf(v1, v2);
#pragma unroll
    for (int o = 16; o > 0; o >>= 1) m = fmaxf(m, __shfl_xor_sync(0xffffffffu, m, o));
    float e1 = expf(v1 - m);
    float e2 = (lane < 24) ? expf(v2 - m) : 0.f;
    float s = e1 + e2;
#pragma unroll
    for (int o = 16; o > 0; o >>= 1) s += __shfl_xor_sync(0xffffffffu, s, o);
    float invs = 1.0f / s;
    out[(size_t)wid * NOUT + lane] = e1 * invs;
    if (lane < 24) out[(size_t)wid * NOUT + 32 + lane] = e2 * invs;
}

// ---------------- launch ----------------
extern "C" void kernel_launch(void* const* d_in, const int* in_sizes, int n_in,
                              void* d_out, int out_size) {
    (void)in_sizes; (void)n_in; (void)out_size;
    const float* x     = (const float*)d_in[0];
    const int*   adj   = (const int*)d_in[1];
    const float* Ws    = (const float*)d_in[2];
    const float* As_   = (const float*)d_in[3];
    const float* W_out = (const float*)d_in[4];
    const float* a_out = (const float*)d_in[5];
    float* out = (float*)d_out;

    cudaFuncSetAttribute(k3_mma, cudaFuncAttributeMaxDynamicSharedMemorySize, K3_SMEM);
    cudaFuncSetAttribute(k5_mma, cudaFuncAttributeMaxDynamicSharedMemorySize, K5_SMEM);

    kA_init<<<2048, 256>>>(x, Ws, adj);
    k1_mma<<<dim3(64, 8), 128>>>(As_);
    k_nop<<<1, 32>>>();
    k3_mma<<<dim3(32, 8), 256, K3_SMEM>>>();
    k4_h2<<<256, 256>>>(W_out, a_out);
    k5_mma<<<dim3(32, 8), 256, K5_SMEM>>>();
    k6_final<<<512, 256>>>(out);
}

// round 16
// speedup vs baseline: 1.6669x; 1.0107x over previous
#include <cuda_runtime.h>
#include <cuda_fp16.h>
#include <math.h>
#include <stdint.h>

#define N 4096
#define NHEADS 8
#define NHID 64
#define NFEAT 512
#define NOUT 56

// ---------------- device scratch ----------------
__device__ __half g_xh[(size_t)N * NFEAT];
__device__ __half g_Wh[(size_t)NHEADS * NFEAT * NHID];
__device__ __half g_Hf16[(size_t)NHEADS * N * NHID];
__device__ uint32_t g_adjbits[(size_t)N * 128];
__device__ __half g_E1h[NHEADS * N], g_E1bh[NHEADS * N];
__device__ __half g_E2h[NHEADS * N], g_E2bh[NHEADS * N];
__device__ float g_Z[N * NHID];
__device__ __half g_H2f16[(size_t)N * 64];   // col 56 = 1.0 (den trick), 57-63 = 0
__device__ __half g_E1oh[N], g_E1boh[N], g_E2oh[N], g_E2boh[N];
__device__ float g_num2[N * NOUT];
__device__ float g_den2[N];

// ---------------- helpers ----------------
__device__ __forceinline__ uint32_t s2u(const void* p) {
    uint32_t a;
    asm("{ .reg .u64 t; cvta.to.shared.u64 t, %1; cvt.u32.u64 %0, t; }" : "=r"(a) : "l"(p));
    return a;
}
#define LDSM_X4(r0, r1, r2, r3, a) \
    asm volatile("ldmatrix.sync.aligned.m8n8.x4.shared.b16 {%0,%1,%2,%3}, [%4];" \
                 : "=r"(r0), "=r"(r1), "=r"(r2), "=r"(r3) : "r"(a))
#define LDSM_X4T(r0, r1, r2, r3, a) \
    asm volatile("ldmatrix.sync.aligned.m8n8.x4.trans.shared.b16 {%0,%1,%2,%3}, [%4];" \
                 : "=r"(r0), "=r"(r1), "=r"(r2), "=r"(r3) : "r"(a))

__device__ __forceinline__ void mma16816(float* c, uint32_t a0, uint32_t a1, uint32_t a2,
                                         uint32_t a3, uint32_t b0, uint32_t b1) {
    asm volatile(
        "mma.sync.aligned.m16n8k16.row.col.f32.f16.f16.f32 "
        "{%0,%1,%2,%3}, {%4,%5,%6,%7}, {%8,%9}, {%0,%1,%2,%3};"
        : "+f"(c[0]), "+f"(c[1]), "+f"(c[2]), "+f"(c[3])
        : "r"(a0), "r"(a1), "r"(a2), "r"(a3), "r"(b0), "r"(b1));
}
__device__ __forceinline__ uint32_t packh2(float lo, float hi) {
    __half2 h = __floats2half2_rn(lo, hi);
    return *(uint32_t*)&h;
}
__device__ __forceinline__ uint32_t h2u(__half2 h) { return *(uint32_t*)&h; }
__device__ __forceinline__ uint32_t bits2mask(uint32_t b) {
    return ((b & 1u) ? 0x0000FFFFu : 0u) | ((b & 2u) ? 0xFFFF0000u : 0u);
}
__device__ __forceinline__ void cpa16(uint32_t dst, const void* src) {
    asm volatile("cp.async.cg.shared.global [%0], [%1], 16;" :: "r"(dst), "l"(src));
}
#define CP_COMMIT() asm volatile("cp.async.commit_group;")
#define CP_WAIT1()  asm volatile("cp.async.wait_group 1;")
#define CP_WAIT2()  asm volatile("cp.async.wait_group 2;")
#define CP_WAIT0()  asm volatile("cp.async.wait_group 0;")

// ---------------- KA: merged init (zero + fp16 convert + adj bitmask) ----------------
__global__ __launch_bounds__(256) void kA_init(const float* __restrict__ x,
                                               const float* __restrict__ Ws,
                                               const int* __restrict__ adj) {
    int t = threadIdx.x;
    int gid = blockIdx.x * 256 + t;
    int stride = gridDim.x * 256;
    int w = gid >> 5, lane = t & 31;
    int row = w >> 2, quarter = w & 3;
    const int4* src = (const int4*)(adj + (size_t)row * N + quarter * 1024);
    uint32_t* dstw = g_adjbits + (size_t)row * 128 + quarter * 32;
#pragma unroll
    for (int it = 0; it < 8; it++) {
        int4 v = src[it * 32 + lane];
        uint32_t nib = (uint32_t)(v.x > 0) | ((uint32_t)(v.y > 0) << 1)
                     | ((uint32_t)(v.z > 0) << 2) | ((uint32_t)(v.w > 0) << 3);
        uint32_t word = nib << (4 * (lane & 7));
        word |= __shfl_xor_sync(0xffffffffu, word, 1);
        word |= __shfl_xor_sync(0xffffffffu, word, 2);
        word |= __shfl_xor_sync(0xffffffffu, word, 4);
        if ((lane & 7) == 0) dstw[it * 4 + (lane >> 3)] = word;
    }
    for (int i = gid; i < N * NFEAT / 2; i += stride) {
        float2 v = ((const float2*)x)[i];
        ((__half2*)g_xh)[i] = __floats2half2_rn(v.x, v.y);
    }
    for (int i = gid; i < NHEADS * NFEAT * NHID / 2; i += stride) {
        float2 v = ((const float2*)Ws)[i];
        ((__half2*)g_Wh)[i] = __floats2half2_rn(v.x, v.y);
    }
    for (int i = gid; i < N * NHID; i += stride) g_Z[i] = 0.f;
    for (int i = gid; i < N * NOUT; i += stride) g_num2[i] = 0.f;
    for (int i = gid; i < N; i += stride) g_den2[i] = 0.f;
}

// ---------------- dummy: keeps k3 in the profiler's capture slot ----------------
__global__ void k_nop() {}

// ---------------- K1: H = x @ Ws, 64x64 tile, 128 threads, fused exp epilogue ----------------
#define K1_AS 80
#define K1_BS 144
__global__ __launch_bounds__(128) void k1_mma(const float* __restrict__ As_) {
    __shared__ __align__(16) char Asm[2][64 * K1_AS];
    __shared__ __align__(16) char Bsm[2][32 * K1_BS];
    __shared__ __align__(16) __half Hsm[64 * 64];
    uint32_t Abase = s2u(Asm), Bbase = s2u(Bsm);
    int t = threadIdx.x, w = t >> 5, l = t & 31;
    int i0 = blockIdx.x * 64;
    int h = blockIdx.y;
    int rbase = (w & 1) * 32;
    int ntb = (w >> 1) * 4;
    float c[2][4][4] = {};
    const __half* wsrc = g_Wh + (size_t)h * NFEAT * NHID;

    auto issue = [&](int buf, int kc) {
#pragma unroll
        for (int p = 0; p < 2; p++) {
            int idx = p * 128 + t;
            int rr = idx >> 2, q = idx & 3;
            cpa16(Abase + buf * (64 * K1_AS) + rr * K1_AS + q * 16,
                  g_xh + (size_t)(i0 + rr) * NFEAT + kc + q * 8);
        }
#pragma unroll
        for (int p = 0; p < 2; p++) {
            int idx = p * 128 + t;
            int rr = idx >> 3, q = idx & 7;
            cpa16(Bbase + buf * (32 * K1_BS) + rr * K1_BS + q * 16,
                  wsrc + (size_t)(kc + rr) * NHID + q * 8);
        }
    };
    issue(0, 0); CP_COMMIT();

    for (int s = 0; s < 16; s++) {
        if (s < 15) { issue((s + 1) & 1, (s + 1) * 32); CP_COMMIT(); CP_WAIT1(); }
        else CP_WAIT0();
        __syncthreads();
        int buf = s & 1;
        uint32_t Ab2 = Abase + buf * (64 * K1_AS);
        uint32_t Bb2 = Bbase + buf * (32 * K1_BS);
        int g = l >> 3;
#pragma unroll
        for (int ks = 0; ks < 2; ks++) {
            uint32_t bq[4][2];
#pragma unroll
            for (int p = 0; p < 2; p++) {
                uint32_t addr = Bb2 + (ks * 16 + (g & 1) * 8 + (l & 7)) * K1_BS
                              + (ntb + p * 2 + (g >> 1)) * 16;
                LDSM_X4T(bq[p * 2][0], bq[p * 2][1], bq[p * 2 + 1][0], bq[p * 2 + 1][1], addr);
            }
#pragma unroll
            for (int rf = 0; rf < 2; rf++) {
                uint32_t a0, a1, a2, a3;
                uint32_t addr = Ab2 + (rbase + rf * 16 + (g & 1) * 8 + (l & 7)) * K1_AS
                              + (ks * 16 + (g >> 1) * 8) * 2;
                LDSM_X4(a0, a1, a2, a3, addr);
#pragma unroll
                for (int nt = 0; nt < 4; nt++)
                    mma16816(c[rf][nt], a0, a1, a2, a3, bq[nt][0], bq[nt][1]);
            }
        }
        __syncthreads();
    }
    __half* dst = g_Hf16 + (size_t)h * N * NHID;
#pragma unroll
    for (int rf = 0; rf < 2; rf++)
#pragma unroll
        for (int nt = 0; nt < 4; nt++) {
            int rl = rbase + rf * 16 + (l >> 2);
            int col = (ntb + nt) * 8 + 2 * (l & 3);
            uint32_t v01 = packh2(c[rf][nt][0], c[rf][nt][1]);
            uint32_t v23 = packh2(c[rf][nt][2], c[rf][nt][3]);
            *(uint32_t*)(dst + (size_t)(i0 + rl) * 64 + col) = v01;
            *(uint32_t*)(dst + (size_t)(i0 + rl + 8) * 64 + col) = v23;
            *(uint32_t*)(Hsm + rl * 64 + col) = v01;
            *(uint32_t*)(Hsm + (rl + 8) * 64 + col) = v23;
        }
    __syncthreads();

    float a1lo = As_[h * 128 + 2 * l], a1hi = As_[h * 128 + 2 * l + 1];
    float a2lo = As_[h * 128 + 64 + 2 * l], a2hi = As_[h * 128 + 64 + 2 * l + 1];
    for (int rr = 0; rr < 16; rr++) {
        int rl = w * 16 + rr;
        __half2 hv = ((__half2*)(Hsm + rl * 64))[l];
        float xl = __low2float(hv), xh = __high2float(hv);
        float s1p = xl * a1lo + xh * a1hi;
        float s2p = xl * a2lo + xh * a2hi;
#pragma unroll
        for (int o = 16; o > 0; o >>= 1) {
            s1p += __shfl_xor_sync(0xffffffffu, s1p, o);
            s2p += __shfl_xor_sync(0xffffffffu, s2p, o);
        }
        if (l == 0) {
            int idx = h * N + i0 + rl;
            g_E1h[idx]  = __float2half(expf(s1p));
            g_E1bh[idx] = __float2half(expf(0.2f * s1p));
            g_E2h[idx]  = __float2half(expf(s2p));
            g_E2bh[idx] = __float2half(expf(0.2f * s2p));
        }
    }
}

// ---------------- K3: layer-1 aggregation; 4 buffers, 1 barrier per 2 chunks ----------------
#define K3_BBYTES 18432                    // per buf: 128j x 144B
#define K3_SCOFF (4 * K3_BBYTES)           // 73728
#define K3_SMEM (K3_SCOFF + 4 * 512)       // 75776
__global__ __launch_bounds__(256, 2) void k3_mma() {
    extern __shared__ __align__(16) char dsm[];
    uint32_t Bb = s2u(dsm);

    int t = threadIdx.x, w = t >> 5, l = t & 31;
    int i0 = blockIdx.x * 128;
    int h = blockIdx.y;
    int rq = w * 16 + (l >> 2);
    int jb = 2 * (l & 3);
    int g = l >> 3;

    // hoisted producer addressing
    int bj = t >> 3, bqv = t & 7;
    const char* src0 = (const char*)(g_Hf16 + ((size_t)h * N + bj) * 64 + bqv * 8);
    uint32_t dst0 = Bb + bj * 144 + bqv * 16;
    int sc_type = (t >> 4) & 1, sc_jj = t & 15;
    const char* scsrc = (const char*)((sc_type ? g_E2bh : g_E2h) + (size_t)h * N + sc_jj * 8);
    uint32_t scdst = Bb + K3_SCOFF + sc_type * 256 + sc_jj * 16;

    __half2 E1x2[2], E1bx2[2];
#pragma unroll
    for (int r = 0; r < 2; r++) {
        int gidx = h * N + i0 + rq + r * 8;
        E1x2[r] = __half2half2(g_E1h[gidx]);
        E1bx2[r] = __half2half2(g_E1bh[gidx]);
    }
    const uint4* adjp0 = (const uint4*)(g_adjbits + (size_t)(i0 + rq) * 128);
    const uint4* adjp1 = (const uint4*)(g_adjbits + (size_t)(i0 + rq + 8) * 128);

    float c[8][4] = {}, cdenA[4] = {}, cdenB[4] = {};
    uint32_t ones_b = (l < 4) ? 0x3C003C00u : 0u;

    auto issue = [&](int buf, int jc) {      // jc = row offset (multiple of 128)
        size_t so = (size_t)jc * 128;        // jc rows * 64 halves * 2B
        uint32_t bo = (uint32_t)buf * K3_BBYTES;
#pragma unroll
        for (int p = 0; p < 4; p++)
            cpa16(dst0 + bo + p * 4608, src0 + so + p * 4096);
        if (t < 32)
            cpa16(scdst + (uint32_t)buf * 512, scsrc + (size_t)jc * 2);
    };
    issue(0, 0);   CP_COMMIT();
    issue(1, 128); CP_COMMIT();
    issue(2, 256); CP_COMMIT();
    issue(3, 384); CP_COMMIT();

    // prefetch adj for chunk 0
    uint4 P0 = adjp0[0];
    uint4 P1 = adjp1[0];

    for (int s = 0; s < 16; s++) {          // pair index; chunks 2s, 2s+1
        CP_WAIT2();
        int bufA = (s & 1) * 2;             // (2s)&3
#pragma unroll
        for (int half = 0; half < 2; half++) {
            int chunk = 2 * s + half;
            int buf = bufA + half;

            uint4 A0 = P0, A1 = P1;
            if (chunk < 31) { P0 = adjp0[chunk + 1]; P1 = adjp1[chunk + 1]; }

            const __half* scE2 = (const __half*)(dsm + K3_SCOFF + buf * 512);
            uint32_t aw0[4] = {A0.x, A0.y, A0.z, A0.w};
            uint32_t aw1[4] = {A1.x, A1.y, A1.z, A1.w};
            uint32_t Bb2 = Bb + buf * K3_BBYTES;
#pragma unroll
            for (int ks = 0; ks < 8; ks++) {
                uint32_t sh = (ks & 1) * 16 + jb;
                uint32_t m0 = aw0[ks >> 1] >> sh;
                uint32_t m1 = aw1[ks >> 1] >> sh;
                uint32_t areg[4];
#pragma unroll
                for (int p = 0; p < 2; p++) {
                    int j0 = ks * 16 + jb + p * 8;
                    __half2 e2  = *(const __half2*)(scE2 + j0);
                    __half2 e2b = *(const __half2*)(scE2 + 128 + j0);
                    __half2 w0 = __hmax2(__hmul2(E1x2[0], e2), __hmul2(E1bx2[0], e2b));
                    __half2 w1 = __hmax2(__hmul2(E1x2[1], e2), __hmul2(E1bx2[1], e2b));
                    areg[p * 2]     = h2u(w0) & bits2mask((m0 >> (p * 8)) & 3u);
                    areg[p * 2 + 1] = h2u(w1) & bits2mask((m1 >> (p * 8)) & 3u);
                }
#pragma unroll
                for (int p = 0; p < 4; p++) {
                    uint32_t b0, b1, b2, b3;
                    uint32_t addr = Bb2 + (ks * 16 + (g & 1) * 8 + (l & 7)) * 144
                                  + (p * 2 + (g >> 1)) * 16;
                    LDSM_X4T(b0, b1, b2, b3, addr);
                    mma16816(c[p * 2],     areg[0], areg[1], areg[2], areg[3], b0, b1);
                    mma16816(c[p * 2 + 1], areg[0], areg[1], areg[2], areg[3], b2, b3);
                }
                if (ks & 1) mma16816(cdenB, areg[0], areg[1], areg[2], areg[3], ones_b, ones_b);
                else        mma16816(cdenA, areg[0], areg[1], areg[2], areg[3], ones_b, ones_b);
            }
        }
        __syncthreads();
        if (s < 14) {
            issue(bufA,     (2 * s + 4) * 128); CP_COMMIT();
            issue(bufA + 1, (2 * s + 5) * 128); CP_COMMIT();
        }
    }

    float den0 = __shfl_sync(0xffffffffu, cdenA[0] + cdenB[0], l & ~3);
    float den1 = __shfl_sync(0xffffffffu, cdenA[2] + cdenB[2], l & ~3);
    float inv0 = 1.f / den0, inv1 = 1.f / den1;
#pragma unroll
    for (int nt = 0; nt < 8; nt++) {
        int col = nt * 8 + jb;
        float va, vb;
        va = c[nt][0] * inv0; va = (va > 0.f) ? va : expm1f(va);
        vb = c[nt][1] * inv0; vb = (vb > 0.f) ? vb : expm1f(vb);
        atomicAdd(&g_Z[(size_t)(i0 + rq) * 64 + col], 0.125f * va);
        atomicAdd(&g_Z[(size_t)(i0 + rq) * 64 + col + 1], 0.125f * vb);
        va = c[nt][2] * inv1; va = (va > 0.f) ? va : expm1f(va);
        vb = c[nt][3] * inv1; vb = (vb > 0.f) ? vb : expm1f(vb);
        atomicAdd(&g_Z[(size_t)(i0 + rq + 8) * 64 + col], 0.125f * va);
        atomicAdd(&g_Z[(size_t)(i0 + rq + 8) * 64 + col + 1], 0.125f * vb);
    }
}

// ---------------- K4: h2 = z @ W_out; padded zs stride (kills 16-way bank conflict) ----------------
#define ZS_STRIDE 68
__global__ __launch_bounds__(256) void k4_h2(const float* __restrict__ W_out,
                                             const float* __restrict__ a_out) {
    __shared__ __align__(16) float Wo[64 * 56];
    __shared__ float ao[112];
    __shared__ __align__(16) float zs[16 * ZS_STRIDE];
    __shared__ float h2s[16 * 56];
    int t = threadIdx.x, w = t >> 5, l = t & 31;
    int i0 = blockIdx.x * 16;
    for (int idx = t; idx < 64 * 56; idx += 256) Wo[idx] = W_out[idx];
    if (t < 112) ao[t] = a_out[t];
    *(float4*)&zs[(t >> 4) * ZS_STRIDE + (t & 15) * 4] =
        *(const float4*)&g_Z[(size_t)(i0 + (t >> 4)) * 64 + (t & 15) * 4];
    __syncthreads();
    if (t < 224) {
        int i = t / 14, c4 = (t % 14) * 4;
        float ax = 0.f, ay = 0.f, az = 0.f, aw2 = 0.f;
#pragma unroll
        for (int k = 0; k < 64; k++) {
            float a = zs[i * ZS_STRIDE + k];
            float4 w4 = *(const float4*)&Wo[k * 56 + c4];
            ax = fmaf(a, w4.x, ax); ay = fmaf(a, w4.y, ay);
            az = fmaf(a, w4.z, az); aw2 = fmaf(a, w4.w, aw2);
        }
        h2s[i * 56 + c4] = ax; h2s[i * 56 + c4 + 1] = ay;
        h2s[i * 56 + c4 + 2] = az; h2s[i * 56 + c4 + 3] = aw2;
        *(uint32_t*)(g_H2f16 + (size_t)(i0 + i) * 64 + c4) = packh2(ax, ay);
        *(uint32_t*)(g_H2f16 + (size_t)(i0 + i) * 64 + c4 + 2) = packh2(az, aw2);
    }
    if (t < 16) g_H2f16[(size_t)(i0 + t) * 64 + 56] = __float2half(1.f);
    if (t >= 32 && t < 144) {
        int u = t - 32;
        g_H2f16[(size_t)(i0 + u / 7) * 64 + 57 + (u % 7)] = __float2half(0.f);
    }
    __syncthreads();
#pragma unroll
    for (int rr = 0; rr < 2; rr++) {
        int row = w * 2 + rr;
        float v1 = h2s[row * 56 + l];
        float v2 = (l < 24) ? h2s[row * 56 + 32 + l] : 0.f;
        float s1 = v1 * ao[l] + ((l < 24) ? v2 * ao[32 + l] : 0.f);
        float s2 = v1 * ao[56 + l] + ((l < 24) ? v2 * ao[88 + l] : 0.f);
#pragma unroll
        for (int o = 16; o > 0; o >>= 1) {
            s1 += __shfl_xor_sync(0xffffffffu, s1, o);
            s2 += __shfl_xor_sync(0xffffffffu, s2, o);
        }
        if (l == 0) {
            int i = i0 + row;
            g_E1oh[i]  = __float2half(expf(s1));
            g_E1boh[i] = __float2half(expf(0.2f * s1));
            g_E2oh[i]  = __float2half(expf(s2));
            g_E2boh[i] = __float2half(expf(0.2f * s2));
        }
    }
}

// ---------------- K5: layer-2 aggregation; chunk=128, hoisted addrs; den = col 56 ----------------
#define K5_BBYTES 18432
#define K5_SCOFF (3 * K5_BBYTES)           // 55296
#define K5_SMEM (K5_SCOFF + 3 * 512)       // 56832
__global__ __launch_bounds__(256, 2) void k5_mma() {
    extern __shared__ __align__(16) char dsm[];
    uint32_t Bb = s2u(dsm);
    int t = threadIdx.x, w = t >> 5, l = t & 31;
    int i0 = blockIdx.x * 128, jbeg = blockIdx.y * 512;
    int rq = w * 16 + (l >> 2);
    int jb = 2 * (l & 3);
    int g = l >> 3;

    int bj = t >> 3, bqv = t & 7;
    const char* src0 = (const char*)(g_H2f16 + (size_t)bj * 64 + bqv * 8);
    uint32_t dst0 = Bb + bj * 144 + bqv * 16;
    int sc_type = (t >> 4) & 1, sc_jj = t & 15;
    const char* scsrc = (const char*)((sc_type ? g_E2boh : g_E2oh) + sc_jj * 8);
    uint32_t scdst = Bb + K5_SCOFF + sc_type * 256 + sc_jj * 16;

    __half2 E1x2[2], E1bx2[2];
#pragma unroll
    for (int r = 0; r < 2; r++) {
        int gidx = i0 + rq + r * 8;
        E1x2[r] = __half2half2(g_E1oh[gidx]);
        E1bx2[r] = __half2half2(g_E1boh[gidx]);
    }
    const uint4* adjp0 = (const uint4*)(g_adjbits + (size_t)(i0 + rq) * 128 + (jbeg >> 5));
    const uint4* adjp1 = (const uint4*)(g_adjbits + (size_t)(i0 + rq + 8) * 128 + (jbeg >> 5));

    float c[8][4] = {};

    auto issue = [&](int buf, int jc) {
        size_t so = (size_t)jc * 128;
        uint32_t bo = (uint32_t)buf * K5_BBYTES;
#pragma unroll
        for (int p = 0; p < 4; p++)
            cpa16(dst0 + bo + p * 4608, src0 + so + p * 4096);
        if (t < 32)
            cpa16(scdst + (uint32_t)buf * 512, scsrc + (size_t)jc * 2);
    };
    issue(0, jbeg);       CP_COMMIT();
    issue(1, jbeg + 128); CP_COMMIT();

    for (int s = 0; s < 4; s++) {
        int buf = s - (s / 3) * 3;
        CP_WAIT1();
        __syncthreads();
        if (s < 2) issue((s + 2) % 3, jbeg + s * 128 + 256);
        CP_COMMIT();

        const __half* scE2 = (const __half*)(dsm + K5_SCOFF + buf * 512);
        uint4 A0 = adjp0[s];
        uint4 A1 = adjp1[s];
        uint32_t aw0[4] = {A0.x, A0.y, A0.z, A0.w};
        uint32_t aw1[4] = {A1.x, A1.y, A1.z, A1.w};
        uint32_t Bb2 = Bb + buf * K5_BBYTES;
#pragma unroll
        for (int ks = 0; ks < 8; ks++) {
            uint32_t sh = (ks & 1) * 16 + jb;
            uint32_t m0 = aw0[ks >> 1] >> sh;
            uint32_t m1 = aw1[ks >> 1] >> sh;
            uint32_t areg[4];
#pragma unroll
            for (int p = 0; p < 2; p++) {
                int j0 = ks * 16 + jb + p * 8;
                __half2 e2  = *(const __half2*)(scE2 + j0);
                __half2 e2b = *(const __half2*)(scE2 + 128 + j0);
                __half2 w0 = __hmax2(__hmul2(E1x2[0], e2), __hmul2(E1bx2[0], e2b));
                __half2 w1 = __hmax2(__hmul2(E1x2[1], e2), __hmul2(E1bx2[1], e2b));
                areg[p * 2]     = h2u(w0) & bits2mask((m0 >> (p * 8)) & 3u);
                areg[p * 2 + 1] = h2u(w1) & bits2mask((m1 >> (p * 8)) & 3u);
            }
#pragma unroll
            for (int p = 0; p < 4; p++) {
                uint32_t b0, b1, b2, b3;
                uint32_t addr = Bb2 + (ks * 16 + (g & 1) * 8 + (l & 7)) * 144
                              + (p * 2 + (g >> 1)) * 16;
                LDSM_X4T(b0, b1, b2, b3, addr);
                mma16816(c[p * 2],     areg[0], areg[1], areg[2], areg[3], b0, b1);
                mma16816(c[p * 2 + 1], areg[0], areg[1], areg[2], areg[3], b2, b3);
            }
        }
    }

    float den0 = __shfl_sync(0xffffffffu, c[7][0], l & ~3);
    float den1 = __shfl_sync(0xffffffffu, c[7][2], l & ~3);
    if ((l & 3) == 0) {
        atomicAdd(&g_den2[i0 + rq], den0);
        atomicAdd(&g_den2[i0 + rq + 8], den1);
    }
#pragma unroll
    for (int nt = 0; nt < 7; nt++) {
        int col = nt * 8 + jb;
        atomicAdd(&g_num2[(size_t)(i0 + rq) * NOUT + col], c[nt][0]);
        atomicAdd(&g_num2[(size_t)(i0 + rq) * NOUT + col + 1], c[nt][1]);
        atomicAdd(&g_num2[(size_t)(i0 + rq + 8) * NOUT + col], c[nt][2]);
        atomicAdd(&g_num2[(size_t)(i0 + rq + 8) * NOUT + col + 1], c[nt][3]);
    }
}

// ---------------- K6: out = softmax(elu(num2/den2)) ----------------
__global__ __launch_bounds__(256) void k6_final(float* __restrict__ out) {
    int wid = (blockIdx.x * 256 + threadIdx.x) >> 5;
    int lane = threadIdx.x & 31;
    if (wid >= N) return;
    float invd = 1.0f / g_den2[wid];
    float v1 = g_num2[(size_t)wid * NOUT + lane] * invd;
    v1 = (v1 > 0.f) ? v1 : expm1f(v1);
    float v2 = -1e30f;
    if (lane < 24) {
        v2 = g_num2[(size_t)wid * NOUT + 32 + lane] * invd;
        v2 = (v2 > 0.f) ? v2 : expm1f(v2);
    }
    float m = fmaxf(v1, v2);
#pragma unroll
    for (int o = 16; o > 0; o >>= 1) m = fmaxf(m, __shfl_xor_sync(0xffffffffu, m, o));
    float e1 = expf(v1 - m);
    float e2 = (lane < 24) ? expf(v2 - m) : 0.f;
    float s = e1 + e2;
#pragma unroll
    for (int o = 16; o > 0; o >>= 1) s += __shfl_xor_sync(0xffffffffu, s, o);
    float invs = 1.0f / s;
    out[(size_t)wid * NOUT + lane] = e1 * invs;
    if (lane < 24) out[(size_t)wid * NOUT + 32 + lane] = e2 * invs;
}

// ---------------- launch ----------------
extern "C" void kernel_launch(void* const* d_in, const int* in_sizes, int n_in,
                              void* d_out, int out_size) {
    (void)in_sizes; (void)n_in; (void)out_size;
    const float* x     = (const float*)d_in[0];
    const int*   adj   = (const int*)d_in[1];
    const float* Ws    = (const float*)d_in[2];
    const float* As_   = (const float*)d_in[3];
    const float* W_out = (const float*)d_in[4];
    const float* a_out = (const float*)d_in[5];
    float* out = (float*)d_out;

    cudaFuncSetAttribute(k3_mma, cudaFuncAttributeMaxDynamicSharedMemorySize, K3_SMEM);
    cudaFuncSetAttribute(k5_mma, cudaFuncAttributeMaxDynamicSharedMemorySize, K5_SMEM);

    kA_init<<<2048, 256>>>(x, Ws, adj);
    k1_mma<<<dim3(64, 8), 128>>>(As_);
    k_nop<<<1, 32>>>();
    k3_mma<<<dim3(32, 8), 256, K3_SMEM>>>();
    k4_h2<<<256, 256>>>(W_out, a_out);
    k5_mma<<<dim3(32, 8), 256, K5_SMEM>>>();
    k6_final<<<512, 256>>>(out);
}

// round 17
// speedup vs baseline: 1.6755x; 1.0051x over previous
#include <cuda_runtime.h>
#include <cuda_fp16.h>
#include <math.h>
#include <stdint.h>

#define N 4096
#define NHEADS 8
#define NHID 64
#define NFEAT 512
#define NOUT 56

// ---------------- device scratch ----------------
__device__ __half g_xh[(size_t)N * NFEAT];
__device__ __half g_Wh[(size_t)NHEADS * NFEAT * NHID];
__device__ __half g_Hf16[(size_t)NHEADS * N * NHID];
__device__ uint32_t g_adjbits[(size_t)N * 128];
__device__ __half g_E1h[NHEADS * N], g_E1bh[NHEADS * N];
__device__ __half g_E2h[NHEADS * N], g_E2bh[NHEADS * N];
__device__ float g_Z[N * NHID];
__device__ __half g_H2f16[(size_t)N * 64];   // col 56 = 1.0 (den trick), 57-63 = 0
__device__ __half g_E1oh[N], g_E1boh[N], g_E2oh[N], g_E2boh[N];
__device__ float g_num2[N * NOUT];
__device__ float g_den2[N];

// ---------------- helpers ----------------
__device__ __forceinline__ uint32_t s2u(const void* p) {
    uint32_t a;
    asm("{ .reg .u64 t; cvta.to.shared.u64 t, %1; cvt.u32.u64 %0, t; }" : "=r"(a) : "l"(p));
    return a;
}
#define LDSM_X4(r0, r1, r2, r3, a) \
    asm volatile("ldmatrix.sync.aligned.m8n8.x4.shared.b16 {%0,%1,%2,%3}, [%4];" \
                 : "=r"(r0), "=r"(r1), "=r"(r2), "=r"(r3) : "r"(a))
#define LDSM_X4T(r0, r1, r2, r3, a) \
    asm volatile("ldmatrix.sync.aligned.m8n8.x4.trans.shared.b16 {%0,%1,%2,%3}, [%4];" \
                 : "=r"(r0), "=r"(r1), "=r"(r2), "=r"(r3) : "r"(a))

__device__ __forceinline__ void mma16816(float* c, uint32_t a0, uint32_t a1, uint32_t a2,
                                         uint32_t a3, uint32_t b0, uint32_t b1) {
    asm volatile(
        "mma.sync.aligned.m16n8k16.row.col.f32.f16.f16.f32 "
        "{%0,%1,%2,%3}, {%4,%5,%6,%7}, {%8,%9}, {%0,%1,%2,%3};"
        : "+f"(c[0]), "+f"(c[1]), "+f"(c[2]), "+f"(c[3])
        : "r"(a0), "r"(a1), "r"(a2), "r"(a3), "r"(b0), "r"(b1));
}
__device__ __forceinline__ uint32_t packh2(float lo, float hi) {
    __half2 h = __floats2half2_rn(lo, hi);
    return *(uint32_t*)&h;
}
__device__ __forceinline__ uint32_t h2u(__half2 h) { return *(uint32_t*)&h; }
__device__ __forceinline__ uint32_t bits2mask(uint32_t b) {
    return ((b & 1u) ? 0x0000FFFFu : 0u) | ((b & 2u) ? 0xFFFF0000u : 0u);
}
__device__ __forceinline__ void cpa16(uint32_t dst, const void* src) {
    asm volatile("cp.async.cg.shared.global [%0], [%1], 16;" :: "r"(dst), "l"(src));
}
__device__ __forceinline__ void red2(float* addr, float a, float b) {
    asm volatile("red.global.add.v2.f32 [%0], {%1, %2};" :: "l"(addr), "f"(a), "f"(b) : "memory");
}
#define CP_COMMIT() asm volatile("cp.async.commit_group;")
#define CP_WAIT1()  asm volatile("cp.async.wait_group 1;")
#define CP_WAIT2()  asm volatile("cp.async.wait_group 2;")
#define CP_WAIT0()  asm volatile("cp.async.wait_group 0;")

// ---------------- KA: merged init (zero + fp16 convert + adj bitmask) ----------------
__global__ __launch_bounds__(256) void kA_init(const float* __restrict__ x,
                                               const float* __restrict__ Ws,
                                               const int* __restrict__ adj) {
    int t = threadIdx.x;
    int gid = blockIdx.x * 256 + t;
    int stride = gridDim.x * 256;
    int w = gid >> 5, lane = t & 31;
    int row = w >> 2, quarter = w & 3;
    const int4* src = (const int4*)(adj + (size_t)row * N + quarter * 1024);
    uint32_t* dstw = g_adjbits + (size_t)row * 128 + quarter * 32;
#pragma unroll
    for (int it = 0; it < 8; it++) {
        int4 v = src[it * 32 + lane];
        uint32_t nib = (uint32_t)(v.x > 0) | ((uint32_t)(v.y > 0) << 1)
                     | ((uint32_t)(v.z > 0) << 2) | ((uint32_t)(v.w > 0) << 3);
        uint32_t word = nib << (4 * (lane & 7));
        word |= __shfl_xor_sync(0xffffffffu, word, 1);
        word |= __shfl_xor_sync(0xffffffffu, word, 2);
        word |= __shfl_xor_sync(0xffffffffu, word, 4);
        if ((lane & 7) == 0) dstw[it * 4 + (lane >> 3)] = word;
    }
    for (int i = gid; i < N * NFEAT / 2; i += stride) {
        float2 v = ((const float2*)x)[i];
        ((__half2*)g_xh)[i] = __floats2half2_rn(v.x, v.y);
    }
    for (int i = gid; i < NHEADS * NFEAT * NHID / 2; i += stride) {
        float2 v = ((const float2*)Ws)[i];
        ((__half2*)g_Wh)[i] = __floats2half2_rn(v.x, v.y);
    }
    for (int i = gid; i < N * NHID; i += stride) g_Z[i] = 0.f;
    for (int i = gid; i < N * NOUT; i += stride) g_num2[i] = 0.f;
    for (int i = gid; i < N; i += stride) g_den2[i] = 0.f;
}

// ---------------- K1: H = x @ Ws, 64x64 tile, 128 threads, fused exp epilogue ----------------
#define K1_AS 80
#define K1_BS 144
__global__ __launch_bounds__(128) void k1_mma(const float* __restrict__ As_) {
    __shared__ __align__(16) char Asm[2][64 * K1_AS];
    __shared__ __align__(16) char Bsm[2][32 * K1_BS];
    __shared__ __align__(16) __half Hsm[64 * 64];
    uint32_t Abase = s2u(Asm), Bbase = s2u(Bsm);
    int t = threadIdx.x, w = t >> 5, l = t & 31;
    int i0 = blockIdx.x * 64;
    int h = blockIdx.y;
    int rbase = (w & 1) * 32;
    int ntb = (w >> 1) * 4;
    float c[2][4][4] = {};
    const __half* wsrc = g_Wh + (size_t)h * NFEAT * NHID;

    auto issue = [&](int buf, int kc) {
#pragma unroll
        for (int p = 0; p < 2; p++) {
            int idx = p * 128 + t;
            int rr = idx >> 2, q = idx & 3;
            cpa16(Abase + buf * (64 * K1_AS) + rr * K1_AS + q * 16,
                  g_xh + (size_t)(i0 + rr) * NFEAT + kc + q * 8);
        }
#pragma unroll
        for (int p = 0; p < 2; p++) {
            int idx = p * 128 + t;
            int rr = idx >> 3, q = idx & 7;
            cpa16(Bbase + buf * (32 * K1_BS) + rr * K1_BS + q * 16,
                  wsrc + (size_t)(kc + rr) * NHID + q * 8);
        }
    };
    issue(0, 0); CP_COMMIT();

    for (int s = 0; s < 16; s++) {
        if (s < 15) { issue((s + 1) & 1, (s + 1) * 32); CP_COMMIT(); CP_WAIT1(); }
        else CP_WAIT0();
        __syncthreads();
        int buf = s & 1;
        uint32_t Ab2 = Abase + buf * (64 * K1_AS);
        uint32_t Bb2 = Bbase + buf * (32 * K1_BS);
        int g = l >> 3;
#pragma unroll
        for (int ks = 0; ks < 2; ks++) {
            uint32_t bq[4][2];
#pragma unroll
            for (int p = 0; p < 2; p++) {
                uint32_t addr = Bb2 + (ks * 16 + (g & 1) * 8 + (l & 7)) * K1_BS
                              + (ntb + p * 2 + (g >> 1)) * 16;
                LDSM_X4T(bq[p * 2][0], bq[p * 2][1], bq[p * 2 + 1][0], bq[p * 2 + 1][1], addr);
            }
#pragma unroll
            for (int rf = 0; rf < 2; rf++) {
                uint32_t a0, a1, a2, a3;
                uint32_t addr = Ab2 + (rbase + rf * 16 + (g & 1) * 8 + (l & 7)) * K1_AS
                              + (ks * 16 + (g >> 1) * 8) * 2;
                LDSM_X4(a0, a1, a2, a3, addr);
#pragma unroll
                for (int nt = 0; nt < 4; nt++)
                    mma16816(c[rf][nt], a0, a1, a2, a3, bq[nt][0], bq[nt][1]);
            }
        }
        __syncthreads();
    }
    __half* dst = g_Hf16 + (size_t)h * N * NHID;
#pragma unroll
    for (int rf = 0; rf < 2; rf++)
#pragma unroll
        for (int nt = 0; nt < 4; nt++) {
            int rl = rbase + rf * 16 + (l >> 2);
            int col = (ntb + nt) * 8 + 2 * (l & 3);
            uint32_t v01 = packh2(c[rf][nt][0], c[rf][nt][1]);
            uint32_t v23 = packh2(c[rf][nt][2], c[rf][nt][3]);
            *(uint32_t*)(dst + (size_t)(i0 + rl) * 64 + col) = v01;
            *(uint32_t*)(dst + (size_t)(i0 + rl + 8) * 64 + col) = v23;
            *(uint32_t*)(Hsm + rl * 64 + col) = v01;
            *(uint32_t*)(Hsm + (rl + 8) * 64 + col) = v23;
        }
    __syncthreads();

    float a1lo = As_[h * 128 + 2 * l], a1hi = As_[h * 128 + 2 * l + 1];
    float a2lo = As_[h * 128 + 64 + 2 * l], a2hi = As_[h * 128 + 64 + 2 * l + 1];
    for (int rr = 0; rr < 16; rr++) {
        int rl = w * 16 + rr;
        __half2 hv = ((__half2*)(Hsm + rl * 64))[l];
        float xl = __low2float(hv), xh = __high2float(hv);
        float s1p = xl * a1lo + xh * a1hi;
        float s2p = xl * a2lo + xh * a2hi;
#pragma unroll
        for (int o = 16; o > 0; o >>= 1) {
            s1p += __shfl_xor_sync(0xffffffffu, s1p, o);
            s2p += __shfl_xor_sync(0xffffffffu, s2p, o);
        }
        if (l == 0) {
            int idx = h * N + i0 + rl;
            g_E1h[idx]  = __float2half(expf(s1p));
            g_E1bh[idx] = __float2half(expf(0.2f * s1p));
            g_E2h[idx]  = __float2half(expf(s2p));
            g_E2bh[idx] = __float2half(expf(0.2f * s2p));
        }
    }
}

// ---------------- K3: layer-1 aggregation; 4 buffers, 1 barrier per 2 chunks ----------------
#define K3_BBYTES 18432                    // per buf: 128j x 144B
#define K3_SCOFF (4 * K3_BBYTES)           // 73728
#define K3_SMEM (K3_SCOFF + 4 * 512)       // 75776
__global__ __launch_bounds__(256, 2) void k3_mma() {
    extern __shared__ __align__(16) char dsm[];
    uint32_t Bb = s2u(dsm);

    int t = threadIdx.x, w = t >> 5, l = t & 31;
    int i0 = blockIdx.x * 128;
    int h = blockIdx.y;
    int rq = w * 16 + (l >> 2);
    int jb = 2 * (l & 3);
    int g = l >> 3;

    // hoisted producer addressing
    int bj = t >> 3, bqv = t & 7;
    const char* src0 = (const char*)(g_Hf16 + ((size_t)h * N + bj) * 64 + bqv * 8);
    uint32_t dst0 = Bb + bj * 144 + bqv * 16;
    int sc_type = (t >> 4) & 1, sc_jj = t & 15;
    const char* scsrc = (const char*)((sc_type ? g_E2bh : g_E2h) + (size_t)h * N + sc_jj * 8);
    uint32_t scdst = Bb + K3_SCOFF + sc_type * 256 + sc_jj * 16;

    __half2 E1x2[2], E1bx2[2];
#pragma unroll
    for (int r = 0; r < 2; r++) {
        int gidx = h * N + i0 + rq + r * 8;
        E1x2[r] = __half2half2(g_E1h[gidx]);
        E1bx2[r] = __half2half2(g_E1bh[gidx]);
    }
    const uint4* adjp0 = (const uint4*)(g_adjbits + (size_t)(i0 + rq) * 128);
    const uint4* adjp1 = (const uint4*)(g_adjbits + (size_t)(i0 + rq + 8) * 128);

    float c[8][4] = {}, cdenA[4] = {}, cdenB[4] = {};
    uint32_t ones_b = (l < 4) ? 0x3C003C00u : 0u;

    auto issue = [&](int buf, int jc) {      // jc = row offset (multiple of 128)
        size_t so = (size_t)jc * 128;        // jc rows * 64 halves * 2B
        uint32_t bo = (uint32_t)buf * K3_BBYTES;
#pragma unroll
        for (int p = 0; p < 4; p++)
            cpa16(dst0 + bo + p * 4608, src0 + so + p * 4096);
        if (t < 32)
            cpa16(scdst + (uint32_t)buf * 512, scsrc + (size_t)jc * 2);
    };
    issue(0, 0);   CP_COMMIT();
    issue(1, 128); CP_COMMIT();
    issue(2, 256); CP_COMMIT();
    issue(3, 384); CP_COMMIT();

    // prefetch adj for chunk 0
    uint4 P0 = adjp0[0];
    uint4 P1 = adjp1[0];

    for (int s = 0; s < 16; s++) {          // pair index; chunks 2s, 2s+1
        CP_WAIT2();
        int bufA = (s & 1) * 2;             // (2s)&3
#pragma unroll
        for (int half = 0; half < 2; half++) {
            int chunk = 2 * s + half;
            int buf = bufA + half;

            uint4 A0 = P0, A1 = P1;
            if (chunk < 31) { P0 = adjp0[chunk + 1]; P1 = adjp1[chunk + 1]; }

            const __half* scE2 = (const __half*)(dsm + K3_SCOFF + buf * 512);
            uint32_t aw0[4] = {A0.x, A0.y, A0.z, A0.w};
            uint32_t aw1[4] = {A1.x, A1.y, A1.z, A1.w};
            uint32_t Bb2 = Bb + buf * K3_BBYTES;
#pragma unroll
            for (int ks = 0; ks < 8; ks++) {
                uint32_t sh = (ks & 1) * 16 + jb;
                uint32_t m0 = aw0[ks >> 1] >> sh;
                uint32_t m1 = aw1[ks >> 1] >> sh;
                uint32_t areg[4];
#pragma unroll
                for (int p = 0; p < 2; p++) {
                    int j0 = ks * 16 + jb + p * 8;
                    __half2 e2  = *(const __half2*)(scE2 + j0);
                    __half2 e2b = *(const __half2*)(scE2 + 128 + j0);
                    __half2 w0 = __hmax2(__hmul2(E1x2[0], e2), __hmul2(E1bx2[0], e2b));
                    __half2 w1 = __hmax2(__hmul2(E1x2[1], e2), __hmul2(E1bx2[1], e2b));
                    areg[p * 2]     = h2u(w0) & bits2mask((m0 >> (p * 8)) & 3u);
                    areg[p * 2 + 1] = h2u(w1) & bits2mask((m1 >> (p * 8)) & 3u);
                }
#pragma unroll
                for (int p = 0; p < 4; p++) {
                    uint32_t b0, b1, b2, b3;
                    uint32_t addr = Bb2 + (ks * 16 + (g & 1) * 8 + (l & 7)) * 144
                                  + (p * 2 + (g >> 1)) * 16;
                    LDSM_X4T(b0, b1, b2, b3, addr);
                    mma16816(c[p * 2],     areg[0], areg[1], areg[2], areg[3], b0, b1);
                    mma16816(c[p * 2 + 1], areg[0], areg[1], areg[2], areg[3], b2, b3);
                }
                if (ks & 1) mma16816(cdenB, areg[0], areg[1], areg[2], areg[3], ones_b, ones_b);
                else        mma16816(cdenA, areg[0], areg[1], areg[2], areg[3], ones_b, ones_b);
            }
        }
        __syncthreads();
        if (s < 14) {
            issue(bufA,     (2 * s + 4) * 128); CP_COMMIT();
            issue(bufA + 1, (2 * s + 5) * 128); CP_COMMIT();
        }
    }

    float den0 = __shfl_sync(0xffffffffu, cdenA[0] + cdenB[0], l & ~3);
    float den1 = __shfl_sync(0xffffffffu, cdenA[2] + cdenB[2], l & ~3);
    float inv0 = 1.f / den0, inv1 = 1.f / den1;
#pragma unroll
    for (int nt = 0; nt < 8; nt++) {
        int col = nt * 8 + jb;
        float va, vb;
        va = c[nt][0] * inv0; va = (va > 0.f) ? va : expm1f(va);
        vb = c[nt][1] * inv0; vb = (vb > 0.f) ? vb : expm1f(vb);
        red2(&g_Z[(size_t)(i0 + rq) * 64 + col], 0.125f * va, 0.125f * vb);
        va = c[nt][2] * inv1; va = (va > 0.f) ? va : expm1f(va);
        vb = c[nt][3] * inv1; vb = (vb > 0.f) ? vb : expm1f(vb);
        red2(&g_Z[(size_t)(i0 + rq + 8) * 64 + col], 0.125f * va, 0.125f * vb);
    }
}

// ---------------- K4: h2 = z @ W_out; padded zs stride (kills 16-way bank conflict) ----------------
#define ZS_STRIDE 68
__global__ __launch_bounds__(256) void k4_h2(const float* __restrict__ W_out,
                                             const float* __restrict__ a_out) {
    __shared__ __align__(16) float Wo[64 * 56];
    __shared__ float ao[112];
    __shared__ __align__(16) float zs[16 * ZS_STRIDE];
    __shared__ float h2s[16 * 56];
    int t = threadIdx.x, w = t >> 5, l = t & 31;
    int i0 = blockIdx.x * 16;
    for (int idx = t; idx < 64 * 56; idx += 256) Wo[idx] = W_out[idx];
    if (t < 112) ao[t] = a_out[t];
    *(float4*)&zs[(t >> 4) * ZS_STRIDE + (t & 15) * 4] =
        *(const float4*)&g_Z[(size_t)(i0 + (t >> 4)) * 64 + (t & 15) * 4];
    __syncthreads();
    if (t < 224) {
        int i = t / 14, c4 = (t % 14) * 4;
        float ax = 0.f, ay = 0.f, az = 0.f, aw2 = 0.f;
#pragma unroll
        for (int k = 0; k < 64; k++) {
            float a = zs[i * ZS_STRIDE + k];
            float4 w4 = *(const float4*)&Wo[k * 56 + c4];
            ax = fmaf(a, w4.x, ax); ay = fmaf(a, w4.y, ay);
            az = fmaf(a, w4.z, az); aw2 = fmaf(a, w4.w, aw2);
        }
        h2s[i * 56 + c4] = ax; h2s[i * 56 + c4 + 1] = ay;
        h2s[i * 56 + c4 + 2] = az; h2s[i * 56 + c4 + 3] = aw2;
        *(uint32_t*)(g_H2f16 + (size_t)(i0 + i) * 64 + c4) = packh2(ax, ay);
        *(uint32_t*)(g_H2f16 + (size_t)(i0 + i) * 64 + c4 + 2) = packh2(az, aw2);
    }
    if (t < 16) g_H2f16[(size_t)(i0 + t) * 64 + 56] = __float2half(1.f);
    if (t >= 32 && t < 144) {
        int u = t - 32;
        g_H2f16[(size_t)(i0 + u / 7) * 64 + 57 + (u % 7)] = __float2half(0.f);
    }
    __syncthreads();
#pragma unroll
    for (int rr = 0; rr < 2; rr++) {
        int row = w * 2 + rr;
        float v1 = h2s[row * 56 + l];
        float v2 = (l < 24) ? h2s[row * 56 + 32 + l] : 0.f;
        float s1 = v1 * ao[l] + ((l < 24) ? v2 * ao[32 + l] : 0.f);
        float s2 = v1 * ao[56 + l] + ((l < 24) ? v2 * ao[88 + l] : 0.f);
#pragma unroll
        for (int o = 16; o > 0; o >>= 1) {
            s1 += __shfl_xor_sync(0xffffffffu, s1, o);
            s2 += __shfl_xor_sync(0xffffffffu, s2, o);
        }
        if (l == 0) {
            int i = i0 + row;
            g_E1oh[i]  = __float2half(expf(s1));
            g_E1boh[i] = __float2half(expf(0.2f * s1));
            g_E2oh[i]  = __float2half(expf(s2));
            g_E2boh[i] = __float2half(expf(0.2f * s2));
        }
    }
}

// ---------------- K5: layer-2 aggregation; chunk=128, hoisted addrs; den = col 56 ----------------
#define K5_BBYTES 18432
#define K5_SCOFF (3 * K5_BBYTES)           // 55296
#define K5_SMEM (K5_SCOFF + 3 * 512)       // 56832
__global__ __launch_bounds__(256, 2) void k5_mma() {
    extern __shared__ __align__(16) char dsm[];
    uint32_t Bb = s2u(dsm);
    int t = threadIdx.x, w = t >> 5, l = t & 31;
    int i0 = blockIdx.x * 128, jbeg = blockIdx.y * 512;
    int rq = w * 16 + (l >> 2);
    int jb = 2 * (l & 3);
    int g = l >> 3;

    int bj = t >> 3, bqv = t & 7;
    const char* src0 = (const char*)(g_H2f16 + (size_t)bj * 64 + bqv * 8);
    uint32_t dst0 = Bb + bj * 144 + bqv * 16;
    int sc_type = (t >> 4) & 1, sc_jj = t & 15;
    const char* scsrc = (const char*)((sc_type ? g_E2boh : g_E2oh) + sc_jj * 8);
    uint32_t scdst = Bb + K5_SCOFF + sc_type * 256 + sc_jj * 16;

    __half2 E1x2[2], E1bx2[2];
#pragma unroll
    for (int r = 0; r < 2; r++) {
        int gidx = i0 + rq + r * 8;
        E1x2[r] = __half2half2(g_E1oh[gidx]);
        E1bx2[r] = __half2half2(g_E1boh[gidx]);
    }
    const uint4* adjp0 = (const uint4*)(g_adjbits + (size_t)(i0 + rq) * 128 + (jbeg >> 5));
    const uint4* adjp1 = (const uint4*)(g_adjbits + (size_t)(i0 + rq + 8) * 128 + (jbeg >> 5));

    float c[8][4] = {};

    auto issue = [&](int buf, int jc) {
        size_t so = (size_t)jc * 128;
        uint32_t bo = (uint32_t)buf * K5_BBYTES;
#pragma unroll
        for (int p = 0; p < 4; p++)
            cpa16(dst0 + bo + p * 4608, src0 + so + p * 4096);
        if (t < 32)
            cpa16(scdst + (uint32_t)buf * 512, scsrc + (size_t)jc * 2);
    };
    issue(0, jbeg);       CP_COMMIT();
    issue(1, jbeg + 128); CP_COMMIT();

    for (int s = 0; s < 4; s++) {
        int buf = s - (s / 3) * 3;
        CP_WAIT1();
        __syncthreads();
        if (s < 2) issue((s + 2) % 3, jbeg + s * 128 + 256);
        CP_COMMIT();

        const __half* scE2 = (const __half*)(dsm + K5_SCOFF + buf * 512);
        uint4 A0 = adjp0[s];
        uint4 A1 = adjp1[s];
        uint32_t aw0[4] = {A0.x, A0.y, A0.z, A0.w};
        uint32_t aw1[4] = {A1.x, A1.y, A1.z, A1.w};
        uint32_t Bb2 = Bb + buf * K5_BBYTES;
#pragma unroll
        for (int ks = 0; ks < 8; ks++) {
            uint32_t sh = (ks & 1) * 16 + jb;
            uint32_t m0 = aw0[ks >> 1] >> sh;
            uint32_t m1 = aw1[ks >> 1] >> sh;
            uint32_t areg[4];
#pragma unroll
            for (int p = 0; p < 2; p++) {
                int j0 = ks * 16 + jb + p * 8;
                __half2 e2  = *(const __half2*)(scE2 + j0);
                __half2 e2b = *(const __half2*)(scE2 + 128 + j0);
                __half2 w0 = __hmax2(__hmul2(E1x2[0], e2), __hmul2(E1bx2[0], e2b));
                __half2 w1 = __hmax2(__hmul2(E1x2[1], e2), __hmul2(E1bx2[1], e2b));
                areg[p * 2]     = h2u(w0) & bits2mask((m0 >> (p * 8)) & 3u);
                areg[p * 2 + 1] = h2u(w1) & bits2mask((m1 >> (p * 8)) & 3u);
            }
#pragma unroll
            for (int p = 0; p < 4; p++) {
                uint32_t b0, b1, b2, b3;
                uint32_t addr = Bb2 + (ks * 16 + (g & 1) * 8 + (l & 7)) * 144
                              + (p * 2 + (g >> 1)) * 16;
                LDSM_X4T(b0, b1, b2, b3, addr);
                mma16816(c[p * 2],     areg[0], areg[1], areg[2], areg[3], b0, b1);
                mma16816(c[p * 2 + 1], areg[0], areg[1], areg[2], areg[3], b2, b3);
            }
        }
    }

    float den0 = __shfl_sync(0xffffffffu, c[7][0], l & ~3);
    float den1 = __shfl_sync(0xffffffffu, c[7][2], l & ~3);
    if ((l & 3) == 0) {
        atomicAdd(&g_den2[i0 + rq], den0);
        atomicAdd(&g_den2[i0 + rq + 8], den1);
    }
#pragma unroll
    for (int nt = 0; nt < 7; nt++) {
        int col = nt * 8 + jb;
        red2(&g_num2[(size_t)(i0 + rq) * NOUT + col], c[nt][0], c[nt][1]);
        red2(&g_num2[(size_t)(i0 + rq + 8) * NOUT + col], c[nt][2], c[nt][3]);
    }
}

// ---------------- K6: out = softmax(elu(num2/den2)) ----------------
__global__ __launch_bounds__(256) void k6_final(float* __restrict__ out) {
    int wid = (blockIdx.x * 256 + threadIdx.x) >> 5;
    int lane = threadIdx.x & 31;
    if (wid >= N) return;
    float invd = 1.0f / g_den2[wid];
    float v1 = g_num2[(size_t)wid * NOUT + lane] * invd;
    v1 = (v1 > 0.f) ? v1 : expm1f(v1);
    float v2 = -1e30f;
    if (lane < 24) {
        v2 = g_num2[(size_t)wid * NOUT + 32 + lane] * invd;
        v2 = (v2 > 0.f) ? v2 : expm1f(v2);
    }
    float m = fmaxf(v1, v2);
#pragma unroll
    for (int o = 16; o > 0; o >>= 1) m = fmaxf(m, __shfl_xor_sync(0xffffffffu, m, o));
    float e1 = expf(v1 - m);
    float e2 = (lane < 24) ? expf(v2 - m) : 0.f;
    float s = e1 + e2;
#pragma unroll
    for (int o = 16; o > 0; o >>= 1) s += __shfl_xor_sync(0xffffffffu, s, o);
    float invs = 1.0f / s;
    out[(size_t)wid * NOUT + lane] = e1 * invs;
    if (lane < 24) out[(size_t)wid * NOUT + 32 + lane] = e2 * invs;
}

// ---------------- launch ----------------
extern "C" void kernel_launch(void* const* d_in, const int* in_sizes, int n_in,
                              void* d_out, int out_size) {
    (void)in_sizes; (void)n_in; (void)out_size;
    const float* x     = (const float*)d_in[0];
    const int*   adj   = (const int*)d_in[1];
    const float* Ws    = (const float*)d_in[2];
    const float* As_   = (const float*)d_in[3];
    const float* W_out = (const float*)d_in[4];
    const float* a_out = (const float*)d_in[5];
    float* out = (float*)d_out;

    cudaFuncSetAttribute(k3_mma, cudaFuncAttributeMaxDynamicSharedMemorySize, K3_SMEM);
    cudaFuncSetAttribute(k5_mma, cudaFuncAttributeMaxDynamicSharedMemorySize, K5_SMEM);

    kA_init<<<2048, 256>>>(x, Ws, adj);
    k1_mma<<<dim3(64, 8), 128>>>(As_);
    k3_mma<<<dim3(32, 8), 256, K3_SMEM>>>();
    k4_h2<<<256, 256>>>(W_out, a_out);
    k5_mma<<<dim3(32, 8), 256, K5_SMEM>>>();
    k6_final<<<512, 256>>>(out);
}